// round 5
// baseline (speedup 1.0000x reference)
#include <cuda_runtime.h>
#include <cuda_bf16.h>
#include <math.h>

#define NN 169343
#define EE_MAX 2400000
#define D_IN 128
#define D_H  256
#define D_OUT 40
#define EPS 1e-5f

// ---------------- scratch (allocation-free: __device__ globals, used by symbol) ----
__device__ float g_deg[NN];
__device__ float g_dinv[NN];
__device__ float g_selfnorm[NN];
__device__ float g_edgenorm[EE_MAX];
__device__ float g_b0[(size_t)NN * D_H];   // H (gemm output)
__device__ float g_b1[(size_t)NN * D_H];   // AGG accumulator
__device__ float g_b2[(size_t)NN * D_H];   // activations

// buffer selector: 0..2 -> device globals, 3 -> external pointer parameter
template <int SEL>
__device__ __forceinline__ float* selbuf(float* ext) {
    if constexpr (SEL == 0) return g_b0;
    else if constexpr (SEL == 1) return g_b1;
    else if constexpr (SEL == 2) return g_b2;
    else return ext;
}
template <int SEL>
__device__ __forceinline__ const float* selbuf_c(const float* ext) {
    if constexpr (SEL == 0) return g_b0;
    else if constexpr (SEL == 1) return g_b1;
    else if constexpr (SEL == 2) return g_b2;
    else return ext;
}

// ---------------- degree / norms ----------------
__global__ void k_init_deg() {
    int i = blockIdx.x * blockDim.x + threadIdx.x;
    if (i < NN) g_deg[i] = 1.0f;  // self loop
}

__global__ void k_deg_add(const int* __restrict__ ei, int E) {
    int e = blockIdx.x * blockDim.x + threadIdx.x;
    if (e < E) {
        int dst = ei[E + e];
        atomicAdd(&g_deg[dst], 1.0f);
    }
}

__global__ void k_norms() {
    int i = blockIdx.x * blockDim.x + threadIdx.x;
    if (i < NN) {
        float d = g_deg[i];
        g_dinv[i]     = rsqrtf(d);
        g_selfnorm[i] = 1.0f / d;
    }
}

__global__ void k_edge_norms(const int* __restrict__ ei, int E) {
    int e = blockIdx.x * blockDim.x + threadIdx.x;
    if (e < E) {
        int src = ei[e];
        int dst = ei[E + e];
        g_edgenorm[e] = g_dinv[src] * g_dinv[dst];
    }
}

// ---------------- SGEMM: g_b0 = A@W ; g_b1 = g_b0 * selfnorm[row] ----------------
// A row-major [Nrows,K], W row-major [K,M]. 64x64 tile, 256 threads, 4x4 microtile.
template <int ASEL>
__global__ void k_gemm(const float* __restrict__ Aext, const float* __restrict__ W,
                       int Nrows, int K, int M) {
    const float* A = selbuf_c<ASEL>(Aext);
    __shared__ float As[16][64];
    __shared__ float Bs[16][64];
    const int tx = threadIdx.x % 16;
    const int ty = threadIdx.x / 16;
    const int rowBase = blockIdx.x * 64;
    const int colBase = blockIdx.y * 64;

    float acc[4][4];
    for (int i = 0; i < 4; i++)
        for (int j = 0; j < 4; j++) acc[i][j] = 0.0f;

    for (int k0 = 0; k0 < K; k0 += 16) {
        for (int i = threadIdx.x; i < 64 * 16; i += 256) {
            int r = i >> 4, c = i & 15;
            int gr = rowBase + r;
            float v = 0.0f;
            if (gr < Nrows) v = A[(size_t)gr * K + (k0 + c)];
            As[c][r] = v;
        }
        for (int i = threadIdx.x; i < 16 * 64; i += 256) {
            int r = i >> 6, c = i & 63;
            int gc = colBase + c;
            float v = 0.0f;
            if (gc < M) v = W[(size_t)(k0 + r) * M + gc];
            Bs[r][c] = v;
        }
        __syncthreads();
#pragma unroll
        for (int kk = 0; kk < 16; kk++) {
            float a[4], b[4];
#pragma unroll
            for (int i = 0; i < 4; i++) a[i] = As[kk][ty * 4 + i];
#pragma unroll
            for (int j = 0; j < 4; j++) b[j] = Bs[kk][tx * 4 + j];
#pragma unroll
            for (int i = 0; i < 4; i++)
#pragma unroll
                for (int j = 0; j < 4; j++) acc[i][j] = fmaf(a[i], b[j], acc[i][j]);
        }
        __syncthreads();
    }

    for (int i = 0; i < 4; i++) {
        int row = rowBase + ty * 4 + i;
        if (row >= Nrows) continue;
        float sn = g_selfnorm[row];
        for (int j = 0; j < 4; j++) {
            int col = colBase + tx * 4 + j;
            if (col < M) {
                float v = acc[i][j];
                g_b0[(size_t)row * M + col] = v;
                g_b1[(size_t)row * M + col] = v * sn;
            }
        }
    }
}

// ---------------- edge aggregation: g_b1[dst] += g_b0[src] * edge_norm -----------
// One warp per edge. C4 = cols/4. Lanes stride over float4 chunks of the row.
template <int C4>
__global__ void k_edge_agg(const int* __restrict__ ei, int E) {
    int warp = (blockIdx.x * blockDim.x + threadIdx.x) >> 5;
    int lane = threadIdx.x & 31;
    if (warp >= E) return;
    int src = ei[warp];
    int dst = ei[E + warp];
    float w = g_edgenorm[warp];
    const float4* hs = (const float4*)(g_b0 + (size_t)src * (C4 * 4));
    float* ad = g_b1 + (size_t)dst * (C4 * 4);
    for (int c = lane; c < C4; c += 32) {
        float4 v = hs[c];
        atomicAdd(ad + c * 4 + 0, v.x * w);
        atomicAdd(ad + c * 4 + 1, v.y * w);
        atomicAdd(ad + c * 4 + 2, v.z * w);
        atomicAdd(ad + c * 4 + 3, v.w * w);
    }
}

// ---------------- BN + ReLU epilogue (cols = 256), reads g_b1 -------------------
template <int OUTSEL>
__global__ void k_bnrelu(const float* __restrict__ b, const float* __restrict__ g,
                         const float* __restrict__ beta, const float* __restrict__ m,
                         const float* __restrict__ var, float* outExt) {
    float* OUT = selbuf<OUTSEL>(outExt);
    long long i = (long long)blockIdx.x * blockDim.x + threadIdx.x;  // float4 index
    long long total = (long long)NN * (D_H / 4);
    if (i >= total) return;
    int c4 = (int)(i % (D_H / 4));
    float4 a  = ((const float4*)g_b1)[i];
    float4 bb = ((const float4*)b)[c4];
    float4 gg = ((const float4*)g)[c4];
    float4 be = ((const float4*)beta)[c4];
    float4 mm = ((const float4*)m)[c4];
    float4 vv = ((const float4*)var)[c4];
    float4 o;
    o.x = fmaxf((a.x + bb.x - mm.x) * rsqrtf(vv.x + EPS) * gg.x + be.x, 0.0f);
    o.y = fmaxf((a.y + bb.y - mm.y) * rsqrtf(vv.y + EPS) * gg.y + be.y, 0.0f);
    o.z = fmaxf((a.z + bb.z - mm.z) * rsqrtf(vv.z + EPS) * gg.z + be.z, 0.0f);
    o.w = fmaxf((a.w + bb.w - mm.w) * rsqrtf(vv.w + EPS) * gg.w + be.w, 0.0f);
    ((float4*)OUT)[i] = o;
}

// ---------------- final: logits = g_b1 + b3; log_softmax over 40 cols -----------
__global__ void k_logsoftmax(const float* __restrict__ b3, float* __restrict__ OUT) {
    int warp = threadIdx.x / 32;
    int lane = threadIdx.x % 32;
    int row = blockIdx.x * 8 + warp;
    if (row >= NN) return;
    const float* p = g_b1 + (size_t)row * D_OUT;
    float x0 = p[lane] + b3[lane];
    float x1 = -1e30f;
    if (lane < 8) x1 = p[32 + lane] + b3[32 + lane];
    float mx = fmaxf(x0, x1);
#pragma unroll
    for (int o = 16; o > 0; o >>= 1)
        mx = fmaxf(mx, __shfl_xor_sync(0xffffffff, mx, o));
    float s = __expf(x0 - mx) + ((lane < 8) ? __expf(x1 - mx) : 0.0f);
#pragma unroll
    for (int o = 16; o > 0; o >>= 1)
        s += __shfl_xor_sync(0xffffffff, s, o);
    float ls = __logf(s);
    float* q = OUT + (size_t)row * D_OUT;
    q[lane] = x0 - mx - ls;
    if (lane < 8) q[32 + lane] = x1 - mx - ls;
}

// ---------------- launch (kernel launches ONLY, no other CUDA API) --------------
extern "C" void kernel_launch(void* const* d_in, const int* in_sizes, int n_in,
                              void* d_out, int out_size) {
    const float* x  = (const float*)d_in[0];
    const int*   ei = (const int*)d_in[1];   // JAX default x64-disabled -> int32!
    const float* W1 = (const float*)d_in[2];
    const float* b1 = (const float*)d_in[3];
    const float* g1 = (const float*)d_in[4];
    const float* be1 = (const float*)d_in[5];
    const float* m1 = (const float*)d_in[6];
    const float* v1 = (const float*)d_in[7];
    const float* W2 = (const float*)d_in[8];
    const float* b2 = (const float*)d_in[9];
    const float* g2 = (const float*)d_in[10];
    const float* be2 = (const float*)d_in[11];
    const float* m2 = (const float*)d_in[12];
    const float* v2 = (const float*)d_in[13];
    const float* W3 = (const float*)d_in[14];
    const float* b3 = (const float*)d_in[15];
    float* out = (float*)d_out;

    int E = in_sizes[1] / 2;

    // embeddings region: d_out tail if harness flattened the tuple into one buffer
    bool emb_in_out = ((long long)out_size >= (long long)NN * (D_OUT + D_H));
    float* emb = out + (size_t)NN * D_OUT;

    const int T = 256;
    int nblk = (NN + T - 1) / T;
    int eblk = (E + T - 1) / T;

    // norms
    k_init_deg<<<nblk, T>>>();
    k_deg_add<<<eblk, T>>>(ei, E);
    k_norms<<<nblk, T>>>();
    k_edge_norms<<<eblk, T>>>(ei, E);

    dim3 gemm_grid_h((NN + 63) / 64, D_H / 64);
    dim3 gemm_grid_o((NN + 63) / 64, 1);
    long long agg_threads = (long long)E * 32;
    int agg_grid = (int)((agg_threads + T - 1) / T);
    long long bn_tot = (long long)NN * (D_H / 4);
    int bn_grid = (int)((bn_tot + T - 1) / T);
    int ls_grid = (NN + 7) / 8;

    // layer 1: g_b0 = x@W1, g_b1 pre-init = g_b0*selfnorm
    k_gemm<3><<<gemm_grid_h, T>>>(x, W1, NN, D_IN, D_H);
    k_edge_agg<D_H / 4><<<agg_grid, T>>>(ei, E);
    k_bnrelu<2><<<bn_grid, T>>>(b1, g1, be1, m1, v1, nullptr);

    // layer 2: reads g_b2
    k_gemm<2><<<gemm_grid_h, T>>>(nullptr, W2, NN, D_H, D_H);
    k_edge_agg<D_H / 4><<<agg_grid, T>>>(ei, E);
    if (emb_in_out)
        k_bnrelu<3><<<bn_grid, T>>>(b2, g2, be2, m2, v2, emb);
    else
        k_bnrelu<2><<<bn_grid, T>>>(b2, g2, be2, m2, v2, nullptr);

    // layer 3 + log_softmax
    if (emb_in_out)
        k_gemm<3><<<gemm_grid_o, T>>>(emb, W3, NN, D_H, D_OUT);
    else
        k_gemm<2><<<gemm_grid_o, T>>>(nullptr, W3, NN, D_H, D_OUT);
    k_edge_agg<D_OUT / 4><<<agg_grid, T>>>(ei, E);
    k_logsoftmax<<<ls_grid, T>>>(b3, out);
}

// round 7
// speedup vs baseline: 2.1314x; 2.1314x over previous
#include <cuda_runtime.h>
#include <cuda_bf16.h>
#include <math.h>

#define NN 169343
#define EE_MAX 2400000
#define D_IN 128
#define D_H  256
#define D_OUT 40
#define EPS 1e-5f

// ---------------- scratch (allocation-free __device__ globals, used by symbol) ----
__device__ float g_deg[NN];
__device__ float g_dinv[NN];
__device__ float g_selfnorm[NN];
__device__ float g_edgenorm[EE_MAX];
__device__ float g_b0[(size_t)NN * D_H];   // H (gemm output)
__device__ float g_b1[(size_t)NN * D_H];   // AGG accumulator / gemm direct output
__device__ float g_b2[(size_t)NN * D_H];   // activations / pre-aggregated input

template <int SEL>
__device__ __forceinline__ float* selbuf(float* ext) {
    if constexpr (SEL == 0) return g_b0;
    else if constexpr (SEL == 1) return g_b1;
    else if constexpr (SEL == 2) return g_b2;
    else return ext;
}
template <int SEL>
__device__ __forceinline__ const float* selbuf_c(const float* ext) {
    if constexpr (SEL == 0) return g_b0;
    else if constexpr (SEL == 1) return g_b1;
    else if constexpr (SEL == 2) return g_b2;
    else return ext;
}

// ---------------- degree / norms ----------------
__global__ void k_init_deg() {
    int i = blockIdx.x * blockDim.x + threadIdx.x;
    if (i < NN) g_deg[i] = 1.0f;  // self loop
}
__global__ void k_deg_add(const int* __restrict__ ei, int E) {
    int e = blockIdx.x * blockDim.x + threadIdx.x;
    if (e < E) atomicAdd(&g_deg[ei[E + e]], 1.0f);
}
__global__ void k_norms() {
    int i = blockIdx.x * blockDim.x + threadIdx.x;
    if (i < NN) {
        float d = g_deg[i];
        g_dinv[i]     = rsqrtf(d);
        g_selfnorm[i] = 1.0f / d;
    }
}
__global__ void k_edge_norms(const int* __restrict__ ei, int E) {
    int e = blockIdx.x * blockDim.x + threadIdx.x;
    if (e < E) g_edgenorm[e] = g_dinv[ei[e]] * g_dinv[ei[E + e]];
}

// ---------------- Z = x * selfnorm[row]  (layer-1 pre-agg init, 128 cols) -------
__global__ void k_selfscale(const float* __restrict__ x) {
    long long i = (long long)blockIdx.x * blockDim.x + threadIdx.x;  // float4 idx
    long long total = (long long)NN * (D_IN / 4);
    if (i >= total) return;
    int row = (int)(i / (D_IN / 4));
    float4 v = ((const float4*)x)[i];
    float s = g_selfnorm[row];
    v.x *= s; v.y *= s; v.z *= s; v.w *= s;
    ((float4*)g_b2)[i] = v;
}

// ---------------- SGEMM 128x64 tile, 256 thr, 8x4 microtile ----------------------
// A row-major [Nrows,K] (K in {128,256}), W row-major [K,M] (M in {40,64*k}).
// PREINIT: write H->g_b0 and AGG-preinit g_b1 = H*selfnorm. Else: write g_b1 only.
template <int ASEL, bool PREINIT>
__global__ void k_gemm128(const float* __restrict__ Aext, const float* __restrict__ W,
                          int Nrows, int K, int M) {
    const float* A = selbuf_c<ASEL>(Aext);
    __shared__ float As[16][128];
    __shared__ float Bs[16][64];
    const int tid = threadIdx.x;
    const int tx = tid & 15;          // 16 col groups of 4
    const int ty = tid >> 4;          // 16 row groups of 8
    const int rowBase = blockIdx.x * 128;
    const int colBase = blockIdx.y * 64;

    float acc[8][4];
#pragma unroll
    for (int i = 0; i < 8; i++)
#pragma unroll
        for (int j = 0; j < 4; j++) acc[i][j] = 0.0f;

    for (int k0 = 0; k0 < K; k0 += 16) {
        // A tile: 128 rows x 16 k = 512 float4
#pragma unroll
        for (int idx = tid; idx < 512; idx += 256) {
            int r = idx >> 2, c4 = idx & 3;
            int gr = rowBase + r;
            float4 v = make_float4(0.f, 0.f, 0.f, 0.f);
            if (gr < Nrows) v = *(const float4*)(A + (size_t)gr * K + k0 + c4 * 4);
            As[c4 * 4 + 0][r] = v.x;
            As[c4 * 4 + 1][r] = v.y;
            As[c4 * 4 + 2][r] = v.z;
            As[c4 * 4 + 3][r] = v.w;
        }
        // B tile: 16 k x 64 cols = 256 float4
        {
            int r = tid >> 4, c4 = tid & 15;
            int gc = colBase + c4 * 4;
            float4 v = make_float4(0.f, 0.f, 0.f, 0.f);
            if (gc < M) v = *(const float4*)(W + (size_t)(k0 + r) * M + gc);
            *(float4*)&Bs[r][c4 * 4] = v;
        }
        __syncthreads();
#pragma unroll
        for (int kk = 0; kk < 16; kk++) {
            float4 a0 = *(const float4*)&As[kk][ty * 8 + 0];
            float4 a1 = *(const float4*)&As[kk][ty * 8 + 4];
            float4 b  = *(const float4*)&Bs[kk][tx * 4];
            float av[8] = {a0.x, a0.y, a0.z, a0.w, a1.x, a1.y, a1.z, a1.w};
            float bv[4] = {b.x, b.y, b.z, b.w};
#pragma unroll
            for (int i = 0; i < 8; i++)
#pragma unroll
                for (int j = 0; j < 4; j++) acc[i][j] = fmaf(av[i], bv[j], acc[i][j]);
        }
        __syncthreads();
    }

#pragma unroll
    for (int i = 0; i < 8; i++) {
        int row = rowBase + ty * 8 + i;
        if (row >= Nrows) continue;
        int col = colBase + tx * 4;
        if (col >= M) continue;
        float4 v = make_float4(acc[i][0], acc[i][1], acc[i][2], acc[i][3]);
        if constexpr (PREINIT) {
            float sn = g_selfnorm[row];
            *(float4*)(g_b0 + (size_t)row * M + col) = v;
            float4 w = make_float4(v.x * sn, v.y * sn, v.z * sn, v.w * sn);
            *(float4*)(g_b1 + (size_t)row * M + col) = w;
        } else {
            *(float4*)(g_b1 + (size_t)row * M + col) = v;
        }
    }
}

// ---------------- edge aggregation: DST[dst] += SRC[src] * edge_norm -------------
// One warp per edge; lanes stride over float4 chunks of the row.
template <int C4, int SRCSEL, int DSTSEL>
__global__ void k_edge_agg(const int* __restrict__ ei, int E,
                           const float* __restrict__ srcExt, float* dstExt) {
    const float* SRC = selbuf_c<SRCSEL>(srcExt);
    float* DST = selbuf<DSTSEL>(dstExt);
    int warp = (blockIdx.x * blockDim.x + threadIdx.x) >> 5;
    int lane = threadIdx.x & 31;
    if (warp >= E) return;
    int src = ei[warp];
    int dst = ei[E + warp];
    float w = g_edgenorm[warp];
    const float4* hs = (const float4*)(SRC + (size_t)src * (C4 * 4));
    float* ad = DST + (size_t)dst * (C4 * 4);
#pragma unroll
    for (int c = lane; c < C4; c += 32) {
        float4 v = hs[c];
        atomicAdd(ad + c * 4 + 0, v.x * w);
        atomicAdd(ad + c * 4 + 1, v.y * w);
        atomicAdd(ad + c * 4 + 2, v.z * w);
        atomicAdd(ad + c * 4 + 3, v.w * w);
    }
}

// ---------------- BN + ReLU epilogue (cols = 256), reads g_b1 --------------------
template <int OUTSEL>
__global__ void k_bnrelu(const float* __restrict__ b, const float* __restrict__ g,
                         const float* __restrict__ beta, const float* __restrict__ m,
                         const float* __restrict__ var, float* outExt) {
    float* OUT = selbuf<OUTSEL>(outExt);
    long long i = (long long)blockIdx.x * blockDim.x + threadIdx.x;  // float4 index
    long long total = (long long)NN * (D_H / 4);
    if (i >= total) return;
    int c4 = (int)(i % (D_H / 4));
    float4 a  = ((const float4*)g_b1)[i];
    float4 bb = ((const float4*)b)[c4];
    float4 gg = ((const float4*)g)[c4];
    float4 be = ((const float4*)beta)[c4];
    float4 mm = ((const float4*)m)[c4];
    float4 vv = ((const float4*)var)[c4];
    float4 o;
    o.x = fmaxf((a.x + bb.x - mm.x) * rsqrtf(vv.x + EPS) * gg.x + be.x, 0.0f);
    o.y = fmaxf((a.y + bb.y - mm.y) * rsqrtf(vv.y + EPS) * gg.y + be.y, 0.0f);
    o.z = fmaxf((a.z + bb.z - mm.z) * rsqrtf(vv.z + EPS) * gg.z + be.z, 0.0f);
    o.w = fmaxf((a.w + bb.w - mm.w) * rsqrtf(vv.w + EPS) * gg.w + be.w, 0.0f);
    ((float4*)OUT)[i] = o;
}

// ---------------- final: logits = g_b1 + b3; log_softmax over 40 cols ------------
__global__ void k_logsoftmax(const float* __restrict__ b3, float* __restrict__ OUT) {
    int warp = threadIdx.x / 32;
    int lane = threadIdx.x % 32;
    int row = blockIdx.x * 8 + warp;
    if (row >= NN) return;
    const float* p = g_b1 + (size_t)row * D_OUT;
    float x0 = p[lane] + b3[lane];
    float x1 = -1e30f;
    if (lane < 8) x1 = p[32 + lane] + b3[32 + lane];
    float mx = fmaxf(x0, x1);
#pragma unroll
    for (int o = 16; o > 0; o >>= 1)
        mx = fmaxf(mx, __shfl_xor_sync(0xffffffff, mx, o));
    float s = __expf(x0 - mx) + ((lane < 8) ? __expf(x1 - mx) : 0.0f);
#pragma unroll
    for (int o = 16; o > 0; o >>= 1)
        s += __shfl_xor_sync(0xffffffff, s, o);
    float ls = __logf(s);
    float* q = OUT + (size_t)row * D_OUT;
    q[lane] = x0 - mx - ls;
    if (lane < 8) q[32 + lane] = x1 - mx - ls;
}

// ---------------- launch (kernel launches ONLY) ----------------------------------
extern "C" void kernel_launch(void* const* d_in, const int* in_sizes, int n_in,
                              void* d_out, int out_size) {
    const float* x  = (const float*)d_in[0];
    const int*   ei = (const int*)d_in[1];   // int32 (JAX x64 disabled)
    const float* W1 = (const float*)d_in[2];
    const float* b1 = (const float*)d_in[3];
    const float* g1 = (const float*)d_in[4];
    const float* be1 = (const float*)d_in[5];
    const float* m1 = (const float*)d_in[6];
    const float* v1 = (const float*)d_in[7];
    const float* W2 = (const float*)d_in[8];
    const float* b2 = (const float*)d_in[9];
    const float* g2 = (const float*)d_in[10];
    const float* be2 = (const float*)d_in[11];
    const float* m2 = (const float*)d_in[12];
    const float* v2 = (const float*)d_in[13];
    const float* W3 = (const float*)d_in[14];
    const float* b3 = (const float*)d_in[15];
    float* out = (float*)d_out;

    int E = in_sizes[1] / 2;

    bool emb_in_out = ((long long)out_size >= (long long)NN * (D_OUT + D_H));
    float* emb = out + (size_t)NN * D_OUT;

    const int T = 256;
    int nblk = (NN + T - 1) / T;
    int eblk = (E + T - 1) / T;
    long long agg_threads = (long long)E * 32;
    int agg_grid = (int)((agg_threads + T - 1) / T);
    long long ss_tot = (long long)NN * (D_IN / 4);
    int ss_grid = (int)((ss_tot + T - 1) / T);
    long long bn_tot = (long long)NN * (D_H / 4);
    int bn_grid = (int)((bn_tot + T - 1) / T);
    int ls_grid = (NN + 7) / 8;
    dim3 gemm_h((NN + 127) / 128, D_H / 64);
    dim3 gemm_o((NN + 127) / 128, 1);

    // norms
    k_init_deg<<<nblk, T>>>();
    k_deg_add<<<eblk, T>>>(ei, E);
    k_norms<<<nblk, T>>>();
    k_edge_norms<<<eblk, T>>>(ei, E);

    // layer 1 (reordered): Z = agg_full(x) in g_b2 (128-wide), then g_b1 = Z@W1
    k_selfscale<<<ss_grid, T>>>(x);
    k_edge_agg<D_IN / 4, 3, 2><<<agg_grid, T>>>(ei, E, x, nullptr);
    k_gemm128<2, false><<<gemm_h, T>>>(nullptr, W1, NN, D_IN, D_H);
    k_bnrelu<2><<<bn_grid, T>>>(b1, g1, be1, m1, v1, nullptr);

    // layer 2: g_b0 = act1@W2, g_b1 preinit = g_b0*selfnorm, then edge agg
    k_gemm128<2, true><<<gemm_h, T>>>(nullptr, W2, NN, D_H, D_H);
    k_edge_agg<D_H / 4, 0, 1><<<agg_grid, T>>>(ei, E, nullptr, nullptr);
    if (emb_in_out)
        k_bnrelu<3><<<bn_grid, T>>>(b2, g2, be2, m2, v2, emb);
    else
        k_bnrelu<2><<<bn_grid, T>>>(b2, g2, be2, m2, v2, nullptr);

    // layer 3: g_b0 = emb@W3 (40 cols), g_b1 preinit, agg, log_softmax
    if (emb_in_out)
        k_gemm128<3, true><<<gemm_o, T>>>(emb, W3, NN, D_H, D_OUT);
    else
        k_gemm128<2, true><<<gemm_o, T>>>(nullptr, W3, NN, D_H, D_OUT);
    k_edge_agg<D_OUT / 4, 0, 1><<<agg_grid, T>>>(ei, E, nullptr, nullptr);
    k_logsoftmax<<<ls_grid, T>>>(b3, out);
}

// round 8
// speedup vs baseline: 4.4948x; 2.1088x over previous
#include <cuda_runtime.h>
#include <cuda_bf16.h>
#include <math.h>

#define NN 169343
#define EE_MAX 2400000
#define D_IN 128
#define D_H  256
#define D_OUT 40
#define EPS 1e-5f
#define NB_SCAN ((NN + 255) / 256)   // 662

// ---------------- scratch (allocation-free __device__ globals) -------------------
__device__ float g_dinv[NN];
__device__ float g_selfnorm[NN];
__device__ int   g_counts[NN];
__device__ int   g_cursor[NN];
__device__ int   g_rowptr[NN + 1];
__device__ int   g_partial[NB_SCAN];
__device__ int   g_csr_src[EE_MAX];
__device__ float g_csr_w[EE_MAX];
__device__ float g_b0[(size_t)NN * D_H];   // H (gemm output)
__device__ float g_b1[(size_t)NN * D_H];   // agg result / gemm direct output
__device__ float g_b2[(size_t)NN * D_H];   // activations / pre-aggregated input

template <int SEL>
__device__ __forceinline__ float* selbuf(float* ext) {
    if constexpr (SEL == 0) return g_b0;
    else if constexpr (SEL == 1) return g_b1;
    else if constexpr (SEL == 2) return g_b2;
    else return ext;
}
template <int SEL>
__device__ __forceinline__ const float* selbuf_c(const float* ext) {
    if constexpr (SEL == 0) return g_b0;
    else if constexpr (SEL == 1) return g_b1;
    else if constexpr (SEL == 2) return g_b2;
    else return ext;
}

// ---------------- CSR build ------------------------------------------------------
__global__ void k_zero_counts() {
    int i = blockIdx.x * blockDim.x + threadIdx.x;
    if (i < NN) g_counts[i] = 0;
}
__global__ void k_count(const int* __restrict__ ei, int E) {
    int e = blockIdx.x * blockDim.x + threadIdx.x;
    if (e < E) atomicAdd(&g_counts[ei[E + e]], 1);
}
// exclusive scan: stage 1 (per-block scan of 256, write exclusive + block sums)
__global__ void k_scan1() {
    __shared__ int s[256];
    int gid = blockIdx.x * 256 + threadIdx.x;
    int v = (gid < NN) ? g_counts[gid] : 0;
    s[threadIdx.x] = v;
    __syncthreads();
#pragma unroll
    for (int off = 1; off < 256; off <<= 1) {
        int t = (threadIdx.x >= off) ? s[threadIdx.x - off] : 0;
        __syncthreads();
        s[threadIdx.x] += t;
        __syncthreads();
    }
    if (gid < NN) g_rowptr[gid] = s[threadIdx.x] - v;   // exclusive
    if (threadIdx.x == 255) g_partial[blockIdx.x] = s[255];
}
// stage 2: single block scans the partials (exclusive, in place)
__global__ void k_scan2() {
    __shared__ int s[1024];
    int v = (threadIdx.x < NB_SCAN) ? g_partial[threadIdx.x] : 0;
    s[threadIdx.x] = v;
    __syncthreads();
#pragma unroll
    for (int off = 1; off < 1024; off <<= 1) {
        int t = (threadIdx.x >= off) ? s[threadIdx.x - off] : 0;
        __syncthreads();
        s[threadIdx.x] += t;
        __syncthreads();
    }
    if (threadIdx.x < NB_SCAN) g_partial[threadIdx.x] = s[threadIdx.x] - v;
}
// stage 3: add block offsets; set rowptr[NN]=E
__global__ void k_scan3(int E) {
    int gid = blockIdx.x * 256 + threadIdx.x;
    if (gid < NN) g_rowptr[gid] += g_partial[blockIdx.x];
    if (gid == 0) g_rowptr[NN] = E;
}
// norms from rowptr (deg = in-count + 1 self loop)
__global__ void k_norms() {
    int i = blockIdx.x * blockDim.x + threadIdx.x;
    if (i < NN) {
        float d = (float)(g_rowptr[i + 1] - g_rowptr[i] + 1);
        g_dinv[i]     = rsqrtf(d);
        g_selfnorm[i] = 1.0f / d;
    }
}
__global__ void k_copy_cursor() {
    int i = blockIdx.x * blockDim.x + threadIdx.x;
    if (i < NN) g_cursor[i] = g_rowptr[i];
}
__global__ void k_fill(const int* __restrict__ ei, int E) {
    int e = blockIdx.x * blockDim.x + threadIdx.x;
    if (e < E) {
        int src = ei[e];
        int dst = ei[E + e];
        int pos = atomicAdd(&g_cursor[dst], 1);
        g_csr_src[pos] = src;
        g_csr_w[pos]   = g_dinv[src] * g_dinv[dst];
    }
}

// ---------------- CSR aggregation: DST[r] = SRC[r]*sn[r] + sum SRC[src]*w --------
// TPR threads per row (TPR >= C4), each active thread owns one float4 column.
template <int C4, int TPR, int SRCSEL, int DSTSEL>
__global__ void k_csr_agg(const float* __restrict__ srcExt, float* dstExt) {
    const float* __restrict__ SRC = selbuf_c<SRCSEL>(srcExt);
    float* DST = selbuf<DSTSEL>(dstExt);
    constexpr int RPB = 256 / TPR;
    int row = blockIdx.x * RPB + threadIdx.x / TPR;
    int c   = threadIdx.x % TPR;
    if (row >= NN || c >= C4) return;

    const float4* srow = (const float4*)(SRC + (size_t)row * (C4 * 4));
    float sn = g_selfnorm[row];
    float4 h = srow[c];
    float4 acc = make_float4(h.x * sn, h.y * sn, h.z * sn, h.w * sn);

    int e0 = g_rowptr[row], e1 = g_rowptr[row + 1];
    for (int e = e0; e < e1; e++) {
        int s  = g_csr_src[e];
        float w = g_csr_w[e];
        float4 v = *((const float4*)(SRC + (size_t)s * (C4 * 4)) + c);
        acc.x = fmaf(v.x, w, acc.x);
        acc.y = fmaf(v.y, w, acc.y);
        acc.z = fmaf(v.z, w, acc.z);
        acc.w = fmaf(v.w, w, acc.w);
    }
    *((float4*)(DST + (size_t)row * (C4 * 4)) + c) = acc;
}

// ---------------- SGEMM 128x128 tile, 256 thr, 8x8 microtile ---------------------
// A row-major [Nrows,K] (K in {128,256}), W row-major [K,M]. Writes OUT only.
template <int ASEL, int OUTSEL>
__global__ void __launch_bounds__(256, 2)
k_gemm128(const float* __restrict__ Aext, const float* __restrict__ W,
          float* outExt, int Nrows, int K, int M) {
    const float* A = selbuf_c<ASEL>(Aext);
    float* OUT = selbuf<OUTSEL>(outExt);
    __shared__ float As[16][128];
    __shared__ float Bs[16][128];
    const int tid = threadIdx.x;
    const int tx = tid & 15;          // 16 col groups of 8
    const int ty = tid >> 4;          // 16 row groups of 8
    const int rowBase = blockIdx.x * 128;
    const int colBase = blockIdx.y * 128;

    float acc[8][8];
#pragma unroll
    for (int i = 0; i < 8; i++)
#pragma unroll
        for (int j = 0; j < 8; j++) acc[i][j] = 0.0f;

    for (int k0 = 0; k0 < K; k0 += 16) {
        // A tile: 128 rows x 16 k = 512 float4 (transposed into As[k][row])
#pragma unroll
        for (int idx = tid; idx < 512; idx += 256) {
            int r = idx >> 2, c4 = idx & 3;
            int gr = rowBase + r;
            float4 v = make_float4(0.f, 0.f, 0.f, 0.f);
            if (gr < Nrows) v = *(const float4*)(A + (size_t)gr * K + k0 + c4 * 4);
            As[c4 * 4 + 0][r] = v.x;
            As[c4 * 4 + 1][r] = v.y;
            As[c4 * 4 + 2][r] = v.z;
            As[c4 * 4 + 3][r] = v.w;
        }
        // B tile: 16 k x 128 cols = 512 float4
#pragma unroll
        for (int idx = tid; idx < 512; idx += 256) {
            int r = idx >> 5, c4 = idx & 31;
            int gc = colBase + c4 * 4;
            float4 v = make_float4(0.f, 0.f, 0.f, 0.f);
            if (gc < M) v = *(const float4*)(W + (size_t)(k0 + r) * M + gc);
            *(float4*)&Bs[r][c4 * 4] = v;
        }
        __syncthreads();
#pragma unroll
        for (int kk = 0; kk < 16; kk++) {
            float4 a0 = *(const float4*)&As[kk][ty * 8 + 0];
            float4 a1 = *(const float4*)&As[kk][ty * 8 + 4];
            float4 b0 = *(const float4*)&Bs[kk][tx * 8 + 0];
            float4 b1 = *(const float4*)&Bs[kk][tx * 8 + 4];
            float av[8] = {a0.x, a0.y, a0.z, a0.w, a1.x, a1.y, a1.z, a1.w};
            float bv[8] = {b0.x, b0.y, b0.z, b0.w, b1.x, b1.y, b1.z, b1.w};
#pragma unroll
            for (int i = 0; i < 8; i++)
#pragma unroll
                for (int j = 0; j < 8; j++) acc[i][j] = fmaf(av[i], bv[j], acc[i][j]);
        }
        __syncthreads();
    }

#pragma unroll
    for (int i = 0; i < 8; i++) {
        int row = rowBase + ty * 8 + i;
        if (row >= Nrows) continue;
#pragma unroll
        for (int jj = 0; jj < 2; jj++) {
            int col = colBase + tx * 8 + jj * 4;
            if (col >= M) continue;
            float4 v = make_float4(acc[i][jj * 4 + 0], acc[i][jj * 4 + 1],
                                   acc[i][jj * 4 + 2], acc[i][jj * 4 + 3]);
            *(float4*)(OUT + (size_t)row * M + col) = v;
        }
    }
}

// ---------------- BN + ReLU epilogue (cols = 256), reads g_b1 --------------------
template <int OUTSEL>
__global__ void k_bnrelu(const float* __restrict__ b, const float* __restrict__ g,
                         const float* __restrict__ beta, const float* __restrict__ m,
                         const float* __restrict__ var, float* outExt) {
    float* OUT = selbuf<OUTSEL>(outExt);
    long long i = (long long)blockIdx.x * blockDim.x + threadIdx.x;  // float4 index
    long long total = (long long)NN * (D_H / 4);
    if (i >= total) return;
    int c4 = (int)(i % (D_H / 4));
    float4 a  = ((const float4*)g_b1)[i];
    float4 bb = ((const float4*)b)[c4];
    float4 gg = ((const float4*)g)[c4];
    float4 be = ((const float4*)beta)[c4];
    float4 mm = ((const float4*)m)[c4];
    float4 vv = ((const float4*)var)[c4];
    float4 o;
    o.x = fmaxf((a.x + bb.x - mm.x) * rsqrtf(vv.x + EPS) * gg.x + be.x, 0.0f);
    o.y = fmaxf((a.y + bb.y - mm.y) * rsqrtf(vv.y + EPS) * gg.y + be.y, 0.0f);
    o.z = fmaxf((a.z + bb.z - mm.z) * rsqrtf(vv.z + EPS) * gg.z + be.z, 0.0f);
    o.w = fmaxf((a.w + bb.w - mm.w) * rsqrtf(vv.w + EPS) * gg.w + be.w, 0.0f);
    ((float4*)OUT)[i] = o;
}

// ---------------- final: logits = g_b1 + b3; log_softmax over 40 cols ------------
__global__ void k_logsoftmax(const float* __restrict__ b3, float* __restrict__ OUT) {
    int warp = threadIdx.x / 32;
    int lane = threadIdx.x % 32;
    int row = blockIdx.x * 8 + warp;
    if (row >= NN) return;
    const float* p = g_b1 + (size_t)row * D_OUT;
    float x0 = p[lane] + b3[lane];
    float x1 = -1e30f;
    if (lane < 8) x1 = p[32 + lane] + b3[32 + lane];
    float mx = fmaxf(x0, x1);
#pragma unroll
    for (int o = 16; o > 0; o >>= 1)
        mx = fmaxf(mx, __shfl_xor_sync(0xffffffff, mx, o));
    float s = __expf(x0 - mx) + ((lane < 8) ? __expf(x1 - mx) : 0.0f);
#pragma unroll
    for (int o = 16; o > 0; o >>= 1)
        s += __shfl_xor_sync(0xffffffff, s, o);
    float ls = __logf(s);
    float* q = OUT + (size_t)row * D_OUT;
    q[lane] = x0 - mx - ls;
    if (lane < 8) q[32 + lane] = x1 - mx - ls;
}

// ---------------- launch (kernel launches ONLY) ----------------------------------
extern "C" void kernel_launch(void* const* d_in, const int* in_sizes, int n_in,
                              void* d_out, int out_size) {
    const float* x  = (const float*)d_in[0];
    const int*   ei = (const int*)d_in[1];   // int32 (JAX x64 disabled)
    const float* W1 = (const float*)d_in[2];
    const float* b1 = (const float*)d_in[3];
    const float* g1 = (const float*)d_in[4];
    const float* be1 = (const float*)d_in[5];
    const float* m1 = (const float*)d_in[6];
    const float* v1 = (const float*)d_in[7];
    const float* W2 = (const float*)d_in[8];
    const float* b2 = (const float*)d_in[9];
    const float* g2 = (const float*)d_in[10];
    const float* be2 = (const float*)d_in[11];
    const float* m2 = (const float*)d_in[12];
    const float* v2 = (const float*)d_in[13];
    const float* W3 = (const float*)d_in[14];
    const float* b3 = (const float*)d_in[15];
    float* out = (float*)d_out;

    int E = in_sizes[1] / 2;

    bool emb_in_out = ((long long)out_size >= (long long)NN * (D_OUT + D_H));
    float* emb = out + (size_t)NN * D_OUT;

    const int T = 256;
    int nblk = (NN + T - 1) / T;      // == NB_SCAN
    int eblk = (E + T - 1) / T;
    long long bn_tot = (long long)NN * (D_H / 4);
    int bn_grid = (int)((bn_tot + T - 1) / T);
    int ls_grid = (NN + 7) / 8;
    dim3 gemm_h((NN + 127) / 128, D_H / 128);
    dim3 gemm_o((NN + 127) / 128, 1);
    int agg128_grid = (NN + 7) / 8;    // TPR=32, 8 rows/block
    int agg256_grid = (NN + 3) / 4;    // TPR=64, 4 rows/block
    int agg40_grid  = (NN + 15) / 16;  // TPR=16, 16 rows/block

    // ---- CSR build ----
    k_zero_counts<<<nblk, T>>>();
    k_count<<<eblk, T>>>(ei, E);
    k_scan1<<<NB_SCAN, 256>>>();
    k_scan2<<<1, 1024>>>();
    k_scan3<<<NB_SCAN, 256>>>(E);
    k_norms<<<nblk, T>>>();
    k_copy_cursor<<<nblk, T>>>();
    k_fill<<<eblk, T>>>(ei, E);

    // ---- layer 1 (reordered): g_b2 = agg(x); g_b1 = g_b2@W1; act -> g_b2 ----
    k_csr_agg<D_IN / 4, 32, 3, 2><<<agg128_grid, T>>>(x, nullptr);
    k_gemm128<2, 1><<<gemm_h, T>>>(nullptr, W1, nullptr, NN, D_IN, D_H);
    k_bnrelu<2><<<bn_grid, T>>>(b1, g1, be1, m1, v1, nullptr);

    // ---- layer 2: g_b0 = act1@W2; g_b1 = agg(g_b0); act -> emb ----
    k_gemm128<2, 0><<<gemm_h, T>>>(nullptr, W2, nullptr, NN, D_H, D_H);
    k_csr_agg<D_H / 4, 64, 0, 1><<<agg256_grid, T>>>(nullptr, nullptr);
    if (emb_in_out)
        k_bnrelu<3><<<bn_grid, T>>>(b2, g2, be2, m2, v2, emb);
    else
        k_bnrelu<2><<<bn_grid, T>>>(b2, g2, be2, m2, v2, nullptr);

    // ---- layer 3: g_b0 = emb@W3 (40 cols); g_b1 = agg(g_b0); log_softmax ----
    if (emb_in_out)
        k_gemm128<3, 0><<<gemm_o, T>>>(emb, W3, nullptr, NN, D_H, D_OUT);
    else
        k_gemm128<2, 0><<<gemm_o, T>>>(nullptr, W3, nullptr, NN, D_H, D_OUT);
    k_csr_agg<D_OUT / 4, 16, 0, 1><<<agg40_grid, T>>>(nullptr, nullptr);
    k_logsoftmax<<<ls_grid, T>>>(b3, out);
}

// round 9
// speedup vs baseline: 4.9878x; 1.1097x over previous
#include <cuda_runtime.h>
#include <cuda_bf16.h>
#include <math.h>

#define NN 169343
#define EE_MAX 2400000
#define D_IN 128
#define D_H  256
#define D_OUT 40
#define EPS 1e-5f
#define NB_SCAN ((NN + 255) / 256)   // 662

// ---------------- scratch (allocation-free __device__ globals) -------------------
__device__ float g_dinv[NN];
__device__ float g_selfnorm[NN];
__device__ int   g_counts[NN];
__device__ int   g_cursor[NN];
__device__ int   g_rowptr[NN + 1];
__device__ int   g_partial[NB_SCAN];
__device__ int   g_csr_src[EE_MAX];
__device__ float g_csr_w[EE_MAX];
__device__ float g_s1[D_H], g_o1[D_H];     // fused BN1 params
__device__ float g_s2[D_H], g_o2[D_H];     // fused BN2 params
__device__ float g_b0[(size_t)NN * D_H];   // H (gemm output)
__device__ float g_b1[(size_t)NN * D_H];   // act1 / logits-agg
__device__ float g_b2[(size_t)NN * D_H];   // agg(x) / emb fallback

template <int SEL>
__device__ __forceinline__ float* selbuf(float* ext) {
    if constexpr (SEL == 0) return g_b0;
    else if constexpr (SEL == 1) return g_b1;
    else if constexpr (SEL == 2) return g_b2;
    else return ext;
}
template <int SEL>
__device__ __forceinline__ const float* selbuf_c(const float* ext) {
    if constexpr (SEL == 0) return g_b0;
    else if constexpr (SEL == 1) return g_b1;
    else if constexpr (SEL == 2) return g_b2;
    else return ext;
}

// ---------------- CSR build ------------------------------------------------------
__global__ void k_zero_counts() {
    int i = blockIdx.x * blockDim.x + threadIdx.x;
    if (i < NN) g_counts[i] = 0;
}
__global__ void k_count(const int* __restrict__ ei, int E) {
    int e = blockIdx.x * blockDim.x + threadIdx.x;
    if (e < E) atomicAdd(&g_counts[ei[E + e]], 1);
}
__global__ void k_scan1() {
    __shared__ int s[256];
    int gid = blockIdx.x * 256 + threadIdx.x;
    int v = (gid < NN) ? g_counts[gid] : 0;
    s[threadIdx.x] = v;
    __syncthreads();
#pragma unroll
    for (int off = 1; off < 256; off <<= 1) {
        int t = (threadIdx.x >= off) ? s[threadIdx.x - off] : 0;
        __syncthreads();
        s[threadIdx.x] += t;
        __syncthreads();
    }
    if (gid < NN) g_rowptr[gid] = s[threadIdx.x] - v;   // exclusive
    if (threadIdx.x == 255) g_partial[blockIdx.x] = s[255];
}
__global__ void k_scan2() {
    __shared__ int s[1024];
    int v = (threadIdx.x < NB_SCAN) ? g_partial[threadIdx.x] : 0;
    s[threadIdx.x] = v;
    __syncthreads();
#pragma unroll
    for (int off = 1; off < 1024; off <<= 1) {
        int t = (threadIdx.x >= off) ? s[threadIdx.x - off] : 0;
        __syncthreads();
        s[threadIdx.x] += t;
        __syncthreads();
    }
    if (threadIdx.x < NB_SCAN) g_partial[threadIdx.x] = s[threadIdx.x] - v;
}
__global__ void k_scan3(int E) {
    int gid = blockIdx.x * 256 + threadIdx.x;
    if (gid < NN) g_rowptr[gid] += g_partial[blockIdx.x];
    if (gid == 0) g_rowptr[NN] = E;
}
// norms + cursor init (deg = in-count + self loop)
__global__ void k_norms() {
    int i = blockIdx.x * blockDim.x + threadIdx.x;
    if (i < NN) {
        int r0 = g_rowptr[i];
        float d = (float)(g_rowptr[i + 1] - r0 + 1);
        g_dinv[i]     = rsqrtf(d);
        g_selfnorm[i] = 1.0f / d;
        g_cursor[i]   = r0;
    }
}
__global__ void k_fill(const int* __restrict__ ei, int E) {
    int e = blockIdx.x * blockDim.x + threadIdx.x;
    if (e < E) {
        int src = ei[e];
        int dst = ei[E + e];
        int pos = atomicAdd(&g_cursor[dst], 1);
        g_csr_src[pos] = src;
        g_csr_w[pos]   = g_dinv[src] * g_dinv[dst];
    }
}
// fused BN params: act = relu(v * s + o);  s = g*rsqrt(var+eps), o = beta + (b-m)*s
__global__ void k_bnparams(const float* __restrict__ b1, const float* __restrict__ g1,
                           const float* __restrict__ be1, const float* __restrict__ m1,
                           const float* __restrict__ v1,
                           const float* __restrict__ b2, const float* __restrict__ g2,
                           const float* __restrict__ be2, const float* __restrict__ m2,
                           const float* __restrict__ v2) {
    int c = threadIdx.x;
    if (c < D_H) {
        float s = g1[c] * rsqrtf(v1[c] + EPS);
        g_s1[c] = s;
        g_o1[c] = be1[c] + (b1[c] - m1[c]) * s;
        s = g2[c] * rsqrtf(v2[c] + EPS);
        g_s2[c] = s;
        g_o2[c] = be2[c] + (b2[c] - m2[c]) * s;
    }
}

// ---------------- CSR aggregation ------------------------------------------------
// DST[r, cols] = SRC[r]*sn[r] + sum SRC[src]*w  over cols [colOff4*4, +C4*4)
// TPR threads per row; ROWST4 = row stride in float4 for BOTH src and dst.
// EPI=1: apply fused BN2+ReLU (g_s2/g_o2) before store.
template <int C4, int TPR, int ROWST4, int SRCSEL, int DSTSEL, int EPI>
__global__ void k_csr_agg(const float* __restrict__ srcExt, float* dstExt, int colOff4) {
    const float* __restrict__ SRC = selbuf_c<SRCSEL>(srcExt);
    float* DST = selbuf<DSTSEL>(dstExt);
    constexpr int RPB = 256 / TPR;
    int row = blockIdx.x * RPB + threadIdx.x / TPR;
    int c   = threadIdx.x % TPR;
    if (row >= NN || c >= C4) return;
    int col4 = colOff4 + c;

    float sn = g_selfnorm[row];
    float4 h = *((const float4*)(SRC + (size_t)row * (ROWST4 * 4)) + col4);
    float4 acc = make_float4(h.x * sn, h.y * sn, h.z * sn, h.w * sn);

    int e0 = g_rowptr[row], e1 = g_rowptr[row + 1];
    for (int e = e0; e < e1; e++) {
        int s  = g_csr_src[e];
        float w = g_csr_w[e];
        float4 v = *((const float4*)(SRC + (size_t)s * (ROWST4 * 4)) + col4);
        acc.x = fmaf(v.x, w, acc.x);
        acc.y = fmaf(v.y, w, acc.y);
        acc.z = fmaf(v.z, w, acc.z);
        acc.w = fmaf(v.w, w, acc.w);
    }
    if constexpr (EPI == 1) {
        float4 s4 = *((const float4*)g_s2 + col4);
        float4 o4 = *((const float4*)g_o2 + col4);
        acc.x = fmaxf(fmaf(acc.x, s4.x, o4.x), 0.0f);
        acc.y = fmaxf(fmaf(acc.y, s4.y, o4.y), 0.0f);
        acc.z = fmaxf(fmaf(acc.z, s4.z, o4.z), 0.0f);
        acc.w = fmaxf(fmaf(acc.w, s4.w, o4.w), 0.0f);
    }
    *((float4*)(DST + (size_t)row * (ROWST4 * 4)) + col4) = acc;
}

// ---------------- SGEMM 128x128 tile, 256 thr, 8x8 microtile ---------------------
// A row-major [Nrows,K], W row-major [K,M]. EPI=1: fused BN1+ReLU (g_s1/g_o1).
template <int ASEL, int OUTSEL, int EPI>
__global__ void __launch_bounds__(256, 2)
k_gemm128(const float* __restrict__ Aext, const float* __restrict__ W,
          float* outExt, int Nrows, int K, int M) {
    const float* A = selbuf_c<ASEL>(Aext);
    float* OUT = selbuf<OUTSEL>(outExt);
    __shared__ float As[16][128];
    __shared__ float Bs[16][128];
    const int tid = threadIdx.x;
    const int tx = tid & 15;
    const int ty = tid >> 4;
    const int rowBase = blockIdx.x * 128;
    const int colBase = blockIdx.y * 128;

    float acc[8][8];
#pragma unroll
    for (int i = 0; i < 8; i++)
#pragma unroll
        for (int j = 0; j < 8; j++) acc[i][j] = 0.0f;

    for (int k0 = 0; k0 < K; k0 += 16) {
#pragma unroll
        for (int idx = tid; idx < 512; idx += 256) {
            int r = idx >> 2, c4 = idx & 3;
            int gr = rowBase + r;
            float4 v = make_float4(0.f, 0.f, 0.f, 0.f);
            if (gr < Nrows) v = *(const float4*)(A + (size_t)gr * K + k0 + c4 * 4);
            As[c4 * 4 + 0][r] = v.x;
            As[c4 * 4 + 1][r] = v.y;
            As[c4 * 4 + 2][r] = v.z;
            As[c4 * 4 + 3][r] = v.w;
        }
#pragma unroll
        for (int idx = tid; idx < 512; idx += 256) {
            int r = idx >> 5, c4 = idx & 31;
            int gc = colBase + c4 * 4;
            float4 v = make_float4(0.f, 0.f, 0.f, 0.f);
            if (gc < M) v = *(const float4*)(W + (size_t)(k0 + r) * M + gc);
            *(float4*)&Bs[r][c4 * 4] = v;
        }
        __syncthreads();
#pragma unroll
        for (int kk = 0; kk < 16; kk++) {
            float4 a0 = *(const float4*)&As[kk][ty * 8 + 0];
            float4 a1 = *(const float4*)&As[kk][ty * 8 + 4];
            float4 b0 = *(const float4*)&Bs[kk][tx * 8 + 0];
            float4 b1 = *(const float4*)&Bs[kk][tx * 8 + 4];
            float av[8] = {a0.x, a0.y, a0.z, a0.w, a1.x, a1.y, a1.z, a1.w};
            float bv[8] = {b0.x, b0.y, b0.z, b0.w, b1.x, b1.y, b1.z, b1.w};
#pragma unroll
            for (int i = 0; i < 8; i++)
#pragma unroll
                for (int j = 0; j < 8; j++) acc[i][j] = fmaf(av[i], bv[j], acc[i][j]);
        }
        __syncthreads();
    }

#pragma unroll
    for (int i = 0; i < 8; i++) {
        int row = rowBase + ty * 8 + i;
        if (row >= Nrows) continue;
#pragma unroll
        for (int jj = 0; jj < 2; jj++) {
            int col = colBase + tx * 8 + jj * 4;
            if (col >= M) continue;
            float4 v = make_float4(acc[i][jj * 4 + 0], acc[i][jj * 4 + 1],
                                   acc[i][jj * 4 + 2], acc[i][jj * 4 + 3]);
            if constexpr (EPI == 1) {
                float4 s4 = *(const float4*)(g_s1 + col);
                float4 o4 = *(const float4*)(g_o1 + col);
                v.x = fmaxf(fmaf(v.x, s4.x, o4.x), 0.0f);
                v.y = fmaxf(fmaf(v.y, s4.y, o4.y), 0.0f);
                v.z = fmaxf(fmaf(v.z, s4.z, o4.z), 0.0f);
                v.w = fmaxf(fmaf(v.w, s4.w, o4.w), 0.0f);
            }
            *(float4*)(OUT + (size_t)row * M + col) = v;
        }
    }
}

// ---------------- final: logits = g_b1 + b3; log_softmax over 40 cols ------------
__global__ void k_logsoftmax(const float* __restrict__ b3, float* __restrict__ OUT) {
    int warp = threadIdx.x / 32;
    int lane = threadIdx.x % 32;
    int row = blockIdx.x * 8 + warp;
    if (row >= NN) return;
    const float* p = g_b1 + (size_t)row * D_OUT;
    float x0 = p[lane] + b3[lane];
    float x1 = -1e30f;
    if (lane < 8) x1 = p[32 + lane] + b3[32 + lane];
    float mx = fmaxf(x0, x1);
#pragma unroll
    for (int o = 16; o > 0; o >>= 1)
        mx = fmaxf(mx, __shfl_xor_sync(0xffffffff, mx, o));
    float s = __expf(x0 - mx) + ((lane < 8) ? __expf(x1 - mx) : 0.0f);
#pragma unroll
    for (int o = 16; o > 0; o >>= 1)
        s += __shfl_xor_sync(0xffffffff, s, o);
    float ls = __logf(s);
    float* q = OUT + (size_t)row * D_OUT;
    q[lane] = x0 - mx - ls;
    if (lane < 8) q[32 + lane] = x1 - mx - ls;
}

// ---------------- launch (kernel launches ONLY) ----------------------------------
extern "C" void kernel_launch(void* const* d_in, const int* in_sizes, int n_in,
                              void* d_out, int out_size) {
    const float* x  = (const float*)d_in[0];
    const int*   ei = (const int*)d_in[1];   // int32 (JAX x64 disabled)
    const float* W1 = (const float*)d_in[2];
    const float* b1 = (const float*)d_in[3];
    const float* g1 = (const float*)d_in[4];
    const float* be1 = (const float*)d_in[5];
    const float* m1 = (const float*)d_in[6];
    const float* v1 = (const float*)d_in[7];
    const float* W2 = (const float*)d_in[8];
    const float* b2 = (const float*)d_in[9];
    const float* g2 = (const float*)d_in[10];
    const float* be2 = (const float*)d_in[11];
    const float* m2 = (const float*)d_in[12];
    const float* v2 = (const float*)d_in[13];
    const float* W3 = (const float*)d_in[14];
    const float* b3 = (const float*)d_in[15];
    float* out = (float*)d_out;

    int E = in_sizes[1] / 2;

    bool emb_in_out = ((long long)out_size >= (long long)NN * (D_OUT + D_H));
    float* emb = out + (size_t)NN * D_OUT;

    const int T = 256;
    int nblk = (NN + T - 1) / T;
    int eblk = (E + T - 1) / T;
    int ls_grid = (NN + 7) / 8;
    dim3 gemm_h((NN + 127) / 128, D_H / 128);
    dim3 gemm_o((NN + 127) / 128, 1);
    int agg32_grid = (NN + 7) / 8;     // TPR=32, 8 rows/block
    int agg40_grid = (NN + 15) / 16;   // TPR=16, 16 rows/block

    // ---- CSR build + BN params ----
    k_zero_counts<<<nblk, T>>>();
    k_count<<<eblk, T>>>(ei, E);
    k_scan1<<<NB_SCAN, 256>>>();
    k_scan2<<<1, 1024>>>();
    k_scan3<<<NB_SCAN, 256>>>(E);
    k_norms<<<nblk, T>>>();
    k_fill<<<eblk, T>>>(ei, E);
    k_bnparams<<<1, 256>>>(b1, g1, be1, m1, v1, b2, g2, be2, m2, v2);

    // ---- layer 1: g_b2 = agg(x) [128 cols]; g_b1 = relu(bn1(g_b2@W1)) ----
    k_csr_agg<32, 32, 32, 3, 2, 0><<<agg32_grid, T>>>(x, nullptr, 0);
    k_gemm128<2, 1, 1><<<gemm_h, T>>>(nullptr, W1, nullptr, NN, D_IN, D_H);

    // ---- layer 2: g_b0 = g_b1@W2; emb = relu(bn2(agg(g_b0))) in 2 column passes --
    k_gemm128<1, 0, 0><<<gemm_h, T>>>(nullptr, W2, nullptr, NN, D_H, D_H);
    if (emb_in_out) {
        k_csr_agg<32, 32, 64, 0, 3, 1><<<agg32_grid, T>>>(nullptr, emb, 0);
        k_csr_agg<32, 32, 64, 0, 3, 1><<<agg32_grid, T>>>(nullptr, emb, 32);
    } else {
        k_csr_agg<32, 32, 64, 0, 2, 1><<<agg32_grid, T>>>(nullptr, nullptr, 0);
        k_csr_agg<32, 32, 64, 0, 2, 1><<<agg32_grid, T>>>(nullptr, nullptr, 32);
    }

    // ---- layer 3: g_b0 = emb@W3 (40 cols); g_b1 = agg(g_b0); log_softmax ----
    if (emb_in_out)
        k_gemm128<3, 0, 0><<<gemm_o, T>>>(emb, W3, nullptr, NN, D_H, D_OUT);
    else
        k_gemm128<2, 0, 0><<<gemm_o, T>>>(nullptr, W3, nullptr, NN, D_H, D_OUT);
    k_csr_agg<10, 16, 10, 0, 1, 0><<<agg40_grid, T>>>(nullptr, nullptr, 0);
    k_logsoftmax<<<ls_grid, T>>>(b3, out);
}

// round 10
// speedup vs baseline: 7.2635x; 1.4563x over previous
#include <cuda_runtime.h>
#include <cuda_bf16.h>
#include <math.h>
#include <stdint.h>

#define NN 169343
#define EE_MAX 2400000
#define D_IN 128
#define D_H  256
#define D_OUT 40
#define EPS 1e-5f
#define NB_SCAN ((NN + 255) / 256)   // 662

// ---------------- scratch (allocation-free __device__ globals) -------------------
__device__ float g_dinv[NN];
__device__ float g_selfnorm[NN];
__device__ int   g_counts[NN];
__device__ int   g_cursor[NN];
__device__ int   g_rowptr[NN + 1];
__device__ int   g_partial[NB_SCAN];
__device__ int   g_csr_src[EE_MAX];
__device__ float g_csr_w[EE_MAX];
__device__ float g_s1[D_H], g_o1[D_H];     // fused BN1 params
__device__ float g_s2[D_H], g_o2[D_H];     // fused BN2 params
__device__ float g_b0[(size_t)NN * D_H];   // H (gemm output)
__device__ float g_b1[(size_t)NN * D_H];   // act1 / logits-agg
__device__ float g_b2[(size_t)NN * D_H];   // agg(x) / emb fallback

template <int SEL>
__device__ __forceinline__ float* selbuf(float* ext) {
    if constexpr (SEL == 0) return g_b0;
    else if constexpr (SEL == 1) return g_b1;
    else if constexpr (SEL == 2) return g_b2;
    else return ext;
}
template <int SEL>
__device__ __forceinline__ const float* selbuf_c(const float* ext) {
    if constexpr (SEL == 0) return g_b0;
    else if constexpr (SEL == 1) return g_b1;
    else if constexpr (SEL == 2) return g_b2;
    else return ext;
}

// ---------------- CSR build ------------------------------------------------------
__global__ void k_zero_counts() {
    int i = blockIdx.x * blockDim.x + threadIdx.x;
    if (i < NN) g_counts[i] = 0;
}
__global__ void k_count(const int* __restrict__ ei, int E) {
    int e = blockIdx.x * blockDim.x + threadIdx.x;
    if (e < E) atomicAdd(&g_counts[ei[E + e]], 1);
}
__global__ void k_scan1() {
    __shared__ int s[256];
    int gid = blockIdx.x * 256 + threadIdx.x;
    int v = (gid < NN) ? g_counts[gid] : 0;
    s[threadIdx.x] = v;
    __syncthreads();
#pragma unroll
    for (int off = 1; off < 256; off <<= 1) {
        int t = (threadIdx.x >= off) ? s[threadIdx.x - off] : 0;
        __syncthreads();
        s[threadIdx.x] += t;
        __syncthreads();
    }
    if (gid < NN) g_rowptr[gid] = s[threadIdx.x] - v;   // exclusive
    if (threadIdx.x == 255) g_partial[blockIdx.x] = s[255];
}
__global__ void k_scan2() {
    __shared__ int s[1024];
    int v = (threadIdx.x < NB_SCAN) ? g_partial[threadIdx.x] : 0;
    s[threadIdx.x] = v;
    __syncthreads();
#pragma unroll
    for (int off = 1; off < 1024; off <<= 1) {
        int t = (threadIdx.x >= off) ? s[threadIdx.x - off] : 0;
        __syncthreads();
        s[threadIdx.x] += t;
        __syncthreads();
    }
    if (threadIdx.x < NB_SCAN) g_partial[threadIdx.x] = s[threadIdx.x] - v;
}
__global__ void k_scan3(int E) {
    int gid = blockIdx.x * 256 + threadIdx.x;
    if (gid < NN) g_rowptr[gid] += g_partial[blockIdx.x];
    if (gid == 0) g_rowptr[NN] = E;
}
__global__ void k_norms() {
    int i = blockIdx.x * blockDim.x + threadIdx.x;
    if (i < NN) {
        int r0 = g_rowptr[i];
        float d = (float)(g_rowptr[i + 1] - r0 + 1);
        g_dinv[i]     = rsqrtf(d);
        g_selfnorm[i] = 1.0f / d;
        g_cursor[i]   = r0;
    }
}
__global__ void k_fill(const int* __restrict__ ei, int E) {
    int e = blockIdx.x * blockDim.x + threadIdx.x;
    if (e < E) {
        int src = ei[e];
        int dst = ei[E + e];
        int pos = atomicAdd(&g_cursor[dst], 1);
        g_csr_src[pos] = src;
        g_csr_w[pos]   = g_dinv[src] * g_dinv[dst];
    }
}
__global__ void k_bnparams(const float* __restrict__ b1, const float* __restrict__ g1,
                           const float* __restrict__ be1, const float* __restrict__ m1,
                           const float* __restrict__ v1,
                           const float* __restrict__ b2, const float* __restrict__ g2,
                           const float* __restrict__ be2, const float* __restrict__ m2,
                           const float* __restrict__ v2) {
    int c = threadIdx.x;
    if (c < D_H) {
        float s = g1[c] * rsqrtf(v1[c] + EPS);
        g_s1[c] = s;
        g_o1[c] = be1[c] + (b1[c] - m1[c]) * s;
        s = g2[c] * rsqrtf(v2[c] + EPS);
        g_s2[c] = s;
        g_o2[c] = be2[c] + (b2[c] - m2[c]) * s;
    }
}

// ---------------- CSR aggregation ------------------------------------------------
template <int C4, int TPR, int ROWST4, int SRCSEL, int DSTSEL, int EPI>
__global__ void k_csr_agg(const float* __restrict__ srcExt, float* dstExt, int colOff4) {
    const float* __restrict__ SRC = selbuf_c<SRCSEL>(srcExt);
    float* DST = selbuf<DSTSEL>(dstExt);
    constexpr int RPB = 256 / TPR;
    int row = blockIdx.x * RPB + threadIdx.x / TPR;
    int c   = threadIdx.x % TPR;
    if (row >= NN || c >= C4) return;
    int col4 = colOff4 + c;

    float sn = g_selfnorm[row];
    float4 h = *((const float4*)(SRC + (size_t)row * (ROWST4 * 4)) + col4);
    float4 acc = make_float4(h.x * sn, h.y * sn, h.z * sn, h.w * sn);

    int e0 = g_rowptr[row], e1 = g_rowptr[row + 1];
    for (int e = e0; e < e1; e++) {
        int s  = g_csr_src[e];
        float w = g_csr_w[e];
        float4 v = *((const float4*)(SRC + (size_t)s * (ROWST4 * 4)) + col4);
        acc.x = fmaf(v.x, w, acc.x);
        acc.y = fmaf(v.y, w, acc.y);
        acc.z = fmaf(v.z, w, acc.z);
        acc.w = fmaf(v.w, w, acc.w);
    }
    if constexpr (EPI == 1) {
        float4 s4 = *((const float4*)g_s2 + col4);
        float4 o4 = *((const float4*)g_o2 + col4);
        acc.x = fmaxf(fmaf(acc.x, s4.x, o4.x), 0.0f);
        acc.y = fmaxf(fmaf(acc.y, s4.y, o4.y), 0.0f);
        acc.z = fmaxf(fmaf(acc.z, s4.z, o4.z), 0.0f);
        acc.w = fmaxf(fmaf(acc.w, s4.w, o4.w), 0.0f);
    }
    *((float4*)(DST + (size_t)row * (ROWST4 * 4)) + col4) = acc;
}

// ---------------- tf32 helpers ---------------------------------------------------
__device__ __forceinline__ uint32_t f2tf32(float f) {
    uint32_t r;
    asm("cvt.rna.tf32.f32 %0, %1;" : "=r"(r) : "f"(f));
    return r;
}
__device__ __forceinline__ void mma_tf32(float* c, const uint32_t* a,
                                         uint32_t b0, uint32_t b1) {
    asm volatile(
        "mma.sync.aligned.m16n8k8.row.col.f32.tf32.tf32.f32 "
        "{%0,%1,%2,%3}, {%4,%5,%6,%7}, {%8,%9}, {%0,%1,%2,%3};"
        : "+f"(c[0]), "+f"(c[1]), "+f"(c[2]), "+f"(c[3])
        : "r"(a[0]), "r"(a[1]), "r"(a[2]), "r"(a[3]), "r"(b0), "r"(b1));
}

// ---------------- TF32 GEMM: 128x128 tile, 8 warps (4x2), warp 32x64 -------------
// A row-major [Nrows,K] (K%32==0), W row-major [K,M] (colBase+128 <= M assumed for
// our launches: M=256). EPI=1: fused BN1+ReLU on store.
template <int ASEL, int OUTSEL, int EPI>
__global__ void __launch_bounds__(256, 2)
k_gemm_tf32(const float* __restrict__ Aext, const float* __restrict__ W,
            float* outExt, int Nrows, int K, int M) {
    const float* A = selbuf_c<ASEL>(Aext);
    float* OUT = selbuf<OUTSEL>(outExt);
    __shared__ uint32_t As[128][36];   // [m][k], pad 32->36 (lane-distinct banks)
    __shared__ uint32_t Bs[32][136];   // [k][n], pad 128->136 (8k+n covers banks)

    const int tid  = threadIdx.x;
    const int warp = tid >> 5;
    const int lane = tid & 31;
    const int warpRow = warp & 3;      // 4 row-warps * 32 rows
    const int warpCol = warp >> 2;     // 2 col-warps * 64 cols
    const int rowBase = blockIdx.x * 128;
    const int colBase = blockIdx.y * 128;
    const int tig = lane & 3;          // thread-in-group
    const int grp = lane >> 2;         // group id

    float acc[2][8][4];
#pragma unroll
    for (int mf = 0; mf < 2; mf++)
#pragma unroll
        for (int nf = 0; nf < 8; nf++)
#pragma unroll
            for (int q = 0; q < 4; q++) acc[mf][nf][q] = 0.0f;

    for (int k0 = 0; k0 < K; k0 += 32) {
        // A: 128 rows x 8 float4 = 1024 chunks
#pragma unroll
        for (int idx = tid; idx < 1024; idx += 256) {
            int m = idx >> 3, c4 = idx & 7;
            int gr = rowBase + m;
            float4 v = make_float4(0.f, 0.f, 0.f, 0.f);
            if (gr < Nrows) v = *(const float4*)(A + (size_t)gr * K + k0 + c4 * 4);
            As[m][c4 * 4 + 0] = f2tf32(v.x);
            As[m][c4 * 4 + 1] = f2tf32(v.y);
            As[m][c4 * 4 + 2] = f2tf32(v.z);
            As[m][c4 * 4 + 3] = f2tf32(v.w);
        }
        // B: 32 k-rows x 32 float4 = 1024 chunks
#pragma unroll
        for (int idx = tid; idx < 1024; idx += 256) {
            int k = idx >> 5, c4 = idx & 31;
            int gc = colBase + c4 * 4;
            float4 v = *(const float4*)(W + (size_t)(k0 + k) * M + gc);
            Bs[k][c4 * 4 + 0] = f2tf32(v.x);
            Bs[k][c4 * 4 + 1] = f2tf32(v.y);
            Bs[k][c4 * 4 + 2] = f2tf32(v.z);
            Bs[k][c4 * 4 + 3] = f2tf32(v.w);
        }
        __syncthreads();
#pragma unroll
        for (int k8 = 0; k8 < 4; k8++) {
            uint32_t a[2][4];
#pragma unroll
            for (int mf = 0; mf < 2; mf++) {
                int mrow = warpRow * 32 + mf * 16 + grp;
                a[mf][0] = As[mrow][k8 * 8 + tig];
                a[mf][1] = As[mrow + 8][k8 * 8 + tig];
                a[mf][2] = As[mrow][k8 * 8 + tig + 4];
                a[mf][3] = As[mrow + 8][k8 * 8 + tig + 4];
            }
#pragma unroll
            for (int nf = 0; nf < 8; nf++) {
                int ncol = warpCol * 64 + nf * 8 + grp;
                uint32_t b0 = Bs[k8 * 8 + tig][ncol];
                uint32_t b1 = Bs[k8 * 8 + tig + 4][ncol];
                mma_tf32(acc[0][nf], a[0], b0, b1);
                mma_tf32(acc[1][nf], a[1], b0, b1);
            }
        }
        __syncthreads();
    }

    // epilogue: c0,c1 -> (row, col..col+1); c2,c3 -> (row+8, col..col+1)
#pragma unroll
    for (int mf = 0; mf < 2; mf++) {
        int row0 = rowBase + warpRow * 32 + mf * 16 + grp;
#pragma unroll
        for (int nf = 0; nf < 8; nf++) {
            int col = colBase + warpCol * 64 + nf * 8 + tig * 2;
            float2 v0 = make_float2(acc[mf][nf][0], acc[mf][nf][1]);
            float2 v1 = make_float2(acc[mf][nf][2], acc[mf][nf][3]);
            if constexpr (EPI == 1) {
                float2 s2 = *(const float2*)(g_s1 + col);
                float2 o2 = *(const float2*)(g_o1 + col);
                v0.x = fmaxf(fmaf(v0.x, s2.x, o2.x), 0.0f);
                v0.y = fmaxf(fmaf(v0.y, s2.y, o2.y), 0.0f);
                v1.x = fmaxf(fmaf(v1.x, s2.x, o2.x), 0.0f);
                v1.y = fmaxf(fmaf(v1.y, s2.y, o2.y), 0.0f);
            }
            if (row0 < Nrows)     *(float2*)(OUT + (size_t)row0 * M + col) = v0;
            if (row0 + 8 < Nrows) *(float2*)(OUT + (size_t)(row0 + 8) * M + col) = v1;
        }
    }
}

// ---------------- FFMA SGEMM (kept for layer 3, M=40) ----------------------------
template <int ASEL, int OUTSEL, int EPI>
__global__ void __launch_bounds__(256, 2)
k_gemm128(const float* __restrict__ Aext, const float* __restrict__ W,
          float* outExt, int Nrows, int K, int M) {
    const float* A = selbuf_c<ASEL>(Aext);
    float* OUT = selbuf<OUTSEL>(outExt);
    __shared__ float As[16][128];
    __shared__ float Bs[16][128];
    const int tid = threadIdx.x;
    const int tx = tid & 15;
    const int ty = tid >> 4;
    const int rowBase = blockIdx.x * 128;
    const int colBase = blockIdx.y * 128;

    float acc[8][8];
#pragma unroll
    for (int i = 0; i < 8; i++)
#pragma unroll
        for (int j = 0; j < 8; j++) acc[i][j] = 0.0f;

    for (int k0 = 0; k0 < K; k0 += 16) {
#pragma unroll
        for (int idx = tid; idx < 512; idx += 256) {
            int r = idx >> 2, c4 = idx & 3;
            int gr = rowBase + r;
            float4 v = make_float4(0.f, 0.f, 0.f, 0.f);
            if (gr < Nrows) v = *(const float4*)(A + (size_t)gr * K + k0 + c4 * 4);
            As[c4 * 4 + 0][r] = v.x;
            As[c4 * 4 + 1][r] = v.y;
            As[c4 * 4 + 2][r] = v.z;
            As[c4 * 4 + 3][r] = v.w;
        }
#pragma unroll
        for (int idx = tid; idx < 512; idx += 256) {
            int r = idx >> 5, c4 = idx & 31;
            int gc = colBase + c4 * 4;
            float4 v = make_float4(0.f, 0.f, 0.f, 0.f);
            if (gc < M) v = *(const float4*)(W + (size_t)(k0 + r) * M + gc);
            *(float4*)&Bs[r][c4 * 4] = v;
        }
        __syncthreads();
#pragma unroll
        for (int kk = 0; kk < 16; kk++) {
            float4 a0 = *(const float4*)&As[kk][ty * 8 + 0];
            float4 a1 = *(const float4*)&As[kk][ty * 8 + 4];
            float4 b0 = *(const float4*)&Bs[kk][tx * 8 + 0];
            float4 b1 = *(const float4*)&Bs[kk][tx * 8 + 4];
            float av[8] = {a0.x, a0.y, a0.z, a0.w, a1.x, a1.y, a1.z, a1.w};
            float bv[8] = {b0.x, b0.y, b0.z, b0.w, b1.x, b1.y, b1.z, b1.w};
#pragma unroll
            for (int i = 0; i < 8; i++)
#pragma unroll
                for (int j = 0; j < 8; j++) acc[i][j] = fmaf(av[i], bv[j], acc[i][j]);
        }
        __syncthreads();
    }

#pragma unroll
    for (int i = 0; i < 8; i++) {
        int row = rowBase + ty * 8 + i;
        if (row >= Nrows) continue;
#pragma unroll
        for (int jj = 0; jj < 2; jj++) {
            int col = colBase + tx * 8 + jj * 4;
            if (col >= M) continue;
            float4 v = make_float4(acc[i][jj * 4 + 0], acc[i][jj * 4 + 1],
                                   acc[i][jj * 4 + 2], acc[i][jj * 4 + 3]);
            if constexpr (EPI == 1) {
                float4 s4 = *(const float4*)(g_s1 + col);
                float4 o4 = *(const float4*)(g_o1 + col);
                v.x = fmaxf(fmaf(v.x, s4.x, o4.x), 0.0f);
                v.y = fmaxf(fmaf(v.y, s4.y, o4.y), 0.0f);
                v.z = fmaxf(fmaf(v.z, s4.z, o4.z), 0.0f);
                v.w = fmaxf(fmaf(v.w, s4.w, o4.w), 0.0f);
            }
            *(float4*)(OUT + (size_t)row * M + col) = v;
        }
    }
}

// ---------------- final: logits = g_b1 + b3; log_softmax over 40 cols ------------
__global__ void k_logsoftmax(const float* __restrict__ b3, float* __restrict__ OUT) {
    int warp = threadIdx.x / 32;
    int lane = threadIdx.x % 32;
    int row = blockIdx.x * 8 + warp;
    if (row >= NN) return;
    const float* p = g_b1 + (size_t)row * D_OUT;
    float x0 = p[lane] + b3[lane];
    float x1 = -1e30f;
    if (lane < 8) x1 = p[32 + lane] + b3[32 + lane];
    float mx = fmaxf(x0, x1);
#pragma unroll
    for (int o = 16; o > 0; o >>= 1)
        mx = fmaxf(mx, __shfl_xor_sync(0xffffffff, mx, o));
    float s = __expf(x0 - mx) + ((lane < 8) ? __expf(x1 - mx) : 0.0f);
#pragma unroll
    for (int o = 16; o > 0; o >>= 1)
        s += __shfl_xor_sync(0xffffffff, s, o);
    float ls = __logf(s);
    float* q = OUT + (size_t)row * D_OUT;
    q[lane] = x0 - mx - ls;
    if (lane < 8) q[32 + lane] = x1 - mx - ls;
}

// ---------------- launch (kernel launches ONLY) ----------------------------------
extern "C" void kernel_launch(void* const* d_in, const int* in_sizes, int n_in,
                              void* d_out, int out_size) {
    const float* x  = (const float*)d_in[0];
    const int*   ei = (const int*)d_in[1];   // int32 (JAX x64 disabled)
    const float* W1 = (const float*)d_in[2];
    const float* b1 = (const float*)d_in[3];
    const float* g1 = (const float*)d_in[4];
    const float* be1 = (const float*)d_in[5];
    const float* m1 = (const float*)d_in[6];
    const float* v1 = (const float*)d_in[7];
    const float* W2 = (const float*)d_in[8];
    const float* b2 = (const float*)d_in[9];
    const float* g2 = (const float*)d_in[10];
    const float* be2 = (const float*)d_in[11];
    const float* m2 = (const float*)d_in[12];
    const float* v2 = (const float*)d_in[13];
    const float* W3 = (const float*)d_in[14];
    const float* b3 = (const float*)d_in[15];
    float* out = (float*)d_out;

    int E = in_sizes[1] / 2;

    bool emb_in_out = ((long long)out_size >= (long long)NN * (D_OUT + D_H));
    float* emb = out + (size_t)NN * D_OUT;

    const int T = 256;
    int nblk = (NN + T - 1) / T;
    int eblk = (E + T - 1) / T;
    int ls_grid = (NN + 7) / 8;
    dim3 gemm_h((NN + 127) / 128, D_H / 128);
    dim3 gemm_o((NN + 127) / 128, 1);
    int agg32_grid = (NN + 7) / 8;     // TPR=32, 8 rows/block
    int agg40_grid = (NN + 15) / 16;   // TPR=16, 16 rows/block

    // ---- CSR build + BN params ----
    k_zero_counts<<<nblk, T>>>();
    k_count<<<eblk, T>>>(ei, E);
    k_scan1<<<NB_SCAN, 256>>>();
    k_scan2<<<1, 1024>>>();
    k_scan3<<<NB_SCAN, 256>>>(E);
    k_norms<<<nblk, T>>>();
    k_fill<<<eblk, T>>>(ei, E);
    k_bnparams<<<1, 256>>>(b1, g1, be1, m1, v1, b2, g2, be2, m2, v2);

    // ---- layer 1: g_b2 = agg(x) [128 cols]; g_b1 = relu(bn1(g_b2@W1)) [tf32] ----
    k_csr_agg<32, 32, 32, 3, 2, 0><<<agg32_grid, T>>>(x, nullptr, 0);
    k_gemm_tf32<2, 1, 1><<<gemm_h, T>>>(nullptr, W1, nullptr, NN, D_IN, D_H);

    // ---- layer 2: g_b0 = g_b1@W2 [tf32]; emb = relu(bn2(agg(g_b0))), 2 passes ---
    k_gemm_tf32<1, 0, 0><<<gemm_h, T>>>(nullptr, W2, nullptr, NN, D_H, D_H);
    if (emb_in_out) {
        k_csr_agg<32, 32, 64, 0, 3, 1><<<agg32_grid, T>>>(nullptr, emb, 0);
        k_csr_agg<32, 32, 64, 0, 3, 1><<<agg32_grid, T>>>(nullptr, emb, 32);
    } else {
        k_csr_agg<32, 32, 64, 0, 2, 1><<<agg32_grid, T>>>(nullptr, nullptr, 0);
        k_csr_agg<32, 32, 64, 0, 2, 1><<<agg32_grid, T>>>(nullptr, nullptr, 32);
    }

    // ---- layer 3: g_b0 = emb@W3 (40 cols, FFMA); g_b1 = agg; log_softmax ----
    if (emb_in_out)
        k_gemm128<3, 0, 0><<<gemm_o, T>>>(emb, W3, nullptr, NN, D_H, D_OUT);
    else
        k_gemm128<2, 0, 0><<<gemm_o, T>>>(nullptr, W3, nullptr, NN, D_H, D_OUT);
    k_csr_agg<10, 16, 10, 0, 1, 0><<<agg40_grid, T>>>(nullptr, nullptr, 0);
    k_logsoftmax<<<ls_grid, T>>>(b3, out);
}

// round 11
// speedup vs baseline: 9.2152x; 1.2687x over previous
#include <cuda_runtime.h>
#include <cuda_bf16.h>
#include <math.h>
#include <stdint.h>

#define NN 169343
#define EE_MAX 2400000
#define D_IN 128
#define D_H  256
#define D_OUT 40
#define EPS 1e-5f
#define NB_SCAN ((NN + 255) / 256)   // 662

// ---------------- scratch (allocation-free __device__ globals) -------------------
__device__ float g_dinv[NN];
__device__ float g_selfnorm[NN];
__device__ int   g_counts[NN];
__device__ int   g_cursor[NN];
__device__ int   g_rowptr[NN + 1];
__device__ int   g_partial[NB_SCAN];
__device__ int   g_csr_src[EE_MAX];
__device__ float g_csr_w[EE_MAX];
__device__ float g_s1[D_H], g_o1[D_H];     // fused BN1 params
__device__ float g_s2[D_H], g_o2[D_H];     // fused BN2 params
__device__ float g_b0[(size_t)NN * D_H];   // H (gemm output)
__device__ float g_b1[(size_t)NN * D_H];   // act1 / logits-agg
__device__ float g_b2[(size_t)NN * D_H];   // agg(x) / emb fallback

template <int SEL>
__device__ __forceinline__ float* selbuf(float* ext) {
    if constexpr (SEL == 0) return g_b0;
    else if constexpr (SEL == 1) return g_b1;
    else if constexpr (SEL == 2) return g_b2;
    else return ext;
}
template <int SEL>
__device__ __forceinline__ const float* selbuf_c(const float* ext) {
    if constexpr (SEL == 0) return g_b0;
    else if constexpr (SEL == 1) return g_b1;
    else if constexpr (SEL == 2) return g_b2;
    else return ext;
}

// ---------------- CSR build ------------------------------------------------------
__global__ void k_zero_counts() {
    int i = blockIdx.x * blockDim.x + threadIdx.x;
    if (i < NN) g_counts[i] = 0;
}
__global__ void k_count(const int* __restrict__ ei, int E) {
    int e = blockIdx.x * blockDim.x + threadIdx.x;
    if (e < E) atomicAdd(&g_counts[ei[E + e]], 1);
}
__global__ void k_scan1() {
    __shared__ int s[256];
    int gid = blockIdx.x * 256 + threadIdx.x;
    int v = (gid < NN) ? g_counts[gid] : 0;
    s[threadIdx.x] = v;
    __syncthreads();
#pragma unroll
    for (int off = 1; off < 256; off <<= 1) {
        int t = (threadIdx.x >= off) ? s[threadIdx.x - off] : 0;
        __syncthreads();
        s[threadIdx.x] += t;
        __syncthreads();
    }
    if (gid < NN) g_rowptr[gid] = s[threadIdx.x] - v;   // exclusive
    if (threadIdx.x == 255) g_partial[blockIdx.x] = s[255];
}
__global__ void k_scan2() {
    __shared__ int s[1024];
    int v = (threadIdx.x < NB_SCAN) ? g_partial[threadIdx.x] : 0;
    s[threadIdx.x] = v;
    __syncthreads();
#pragma unroll
    for (int off = 1; off < 1024; off <<= 1) {
        int t = (threadIdx.x >= off) ? s[threadIdx.x - off] : 0;
        __syncthreads();
        s[threadIdx.x] += t;
        __syncthreads();
    }
    if (threadIdx.x < NB_SCAN) g_partial[threadIdx.x] = s[threadIdx.x] - v;
}
__global__ void k_scan3(int E) {
    int gid = blockIdx.x * 256 + threadIdx.x;
    if (gid < NN) g_rowptr[gid] += g_partial[blockIdx.x];
    if (gid == 0) g_rowptr[NN] = E;
}
__global__ void k_norms() {
    int i = blockIdx.x * blockDim.x + threadIdx.x;
    if (i < NN) {
        int r0 = g_rowptr[i];
        float d = (float)(g_rowptr[i + 1] - r0 + 1);
        g_dinv[i]     = rsqrtf(d);
        g_selfnorm[i] = 1.0f / d;
        g_cursor[i]   = r0;
    }
}
__global__ void k_fill(const int* __restrict__ ei, int E) {
    int e = blockIdx.x * blockDim.x + threadIdx.x;
    if (e < E) {
        int src = ei[e];
        int dst = ei[E + e];
        int pos = atomicAdd(&g_cursor[dst], 1);
        g_csr_src[pos] = src;
        g_csr_w[pos]   = g_dinv[src] * g_dinv[dst];
    }
}
__global__ void k_bnparams(const float* __restrict__ b1, const float* __restrict__ g1,
                           const float* __restrict__ be1, const float* __restrict__ m1,
                           const float* __restrict__ v1,
                           const float* __restrict__ b2, const float* __restrict__ g2,
                           const float* __restrict__ be2, const float* __restrict__ m2,
                           const float* __restrict__ v2) {
    int c = threadIdx.x;
    if (c < D_H) {
        float s = g1[c] * rsqrtf(v1[c] + EPS);
        g_s1[c] = s;
        g_o1[c] = be1[c] + (b1[c] - m1[c]) * s;
        s = g2[c] * rsqrtf(v2[c] + EPS);
        g_s2[c] = s;
        g_o2[c] = be2[c] + (b2[c] - m2[c]) * s;
    }
}

// ---------------- CSR aggregation ------------------------------------------------
template <int C4, int TPR, int ROWST4, int SRCSEL, int DSTSEL, int EPI>
__global__ void k_csr_agg(const float* __restrict__ srcExt, float* dstExt, int colOff4) {
    const float* __restrict__ SRC = selbuf_c<SRCSEL>(srcExt);
    float* DST = selbuf<DSTSEL>(dstExt);
    constexpr int RPB = 256 / TPR;
    int row = blockIdx.x * RPB + threadIdx.x / TPR;
    int c   = threadIdx.x % TPR;
    if (row >= NN || c >= C4) return;
    int col4 = colOff4 + c;

    float sn = g_selfnorm[row];
    float4 h = *((const float4*)(SRC + (size_t)row * (ROWST4 * 4)) + col4);
    float4 acc = make_float4(h.x * sn, h.y * sn, h.z * sn, h.w * sn);

    int e0 = g_rowptr[row], e1 = g_rowptr[row + 1];
    for (int e = e0; e < e1; e++) {
        int s  = g_csr_src[e];
        float w = g_csr_w[e];
        float4 v = *((const float4*)(SRC + (size_t)s * (ROWST4 * 4)) + col4);
        acc.x = fmaf(v.x, w, acc.x);
        acc.y = fmaf(v.y, w, acc.y);
        acc.z = fmaf(v.z, w, acc.z);
        acc.w = fmaf(v.w, w, acc.w);
    }
    if constexpr (EPI == 1) {
        float4 s4 = *((const float4*)g_s2 + col4);
        float4 o4 = *((const float4*)g_o2 + col4);
        acc.x = fmaxf(fmaf(acc.x, s4.x, o4.x), 0.0f);
        acc.y = fmaxf(fmaf(acc.y, s4.y, o4.y), 0.0f);
        acc.z = fmaxf(fmaf(acc.z, s4.z, o4.z), 0.0f);
        acc.w = fmaxf(fmaf(acc.w, s4.w, o4.w), 0.0f);
    }
    *((float4*)(DST + (size_t)row * (ROWST4 * 4)) + col4) = acc;
}

// ---------------- tf32 helpers ---------------------------------------------------
__device__ __forceinline__ uint32_t f2tf32(float f) {
    uint32_t r;
    asm("cvt.rna.tf32.f32 %0, %1;" : "=r"(r) : "f"(f));
    return r;
}
__device__ __forceinline__ void mma_tf32(float* c, const uint32_t* a,
                                         uint32_t b0, uint32_t b1) {
    asm volatile(
        "mma.sync.aligned.m16n8k8.row.col.f32.tf32.tf32.f32 "
        "{%0,%1,%2,%3}, {%4,%5,%6,%7}, {%8,%9}, {%0,%1,%2,%3};"
        : "+f"(c[0]), "+f"(c[1]), "+f"(c[2]), "+f"(c[3])
        : "r"(a[0]), "r"(a[1]), "r"(a[2]), "r"(a[3]), "r"(b0), "r"(b1));
}

// ---------------- TF32 GEMM: 128x128 tile, 8 warps (4x2), warp 32x64 -------------
// Software-pipelined: next K-slab prefetched to registers during MMA.
// A row-major [Nrows,K] (K%32==0), W row-major [K,M] (M=256 for our launches).
template <int ASEL, int OUTSEL, int EPI>
__global__ void __launch_bounds__(256, 2)
k_gemm_tf32(const float* __restrict__ Aext, const float* __restrict__ W,
            float* outExt, int Nrows, int K, int M) {
    const float* A = selbuf_c<ASEL>(Aext);
    float* OUT = selbuf<OUTSEL>(outExt);
    __shared__ uint32_t As[128][36];   // [m][k], pad 32->36
    __shared__ uint32_t Bs[32][136];   // [k][n], pad 128->136

    const int tid  = threadIdx.x;
    const int warp = tid >> 5;
    const int lane = tid & 31;
    const int warpRow = warp & 3;
    const int warpCol = warp >> 2;
    const int rowBase = blockIdx.x * 128;
    const int colBase = blockIdx.y * 128;
    const int tig = lane & 3;
    const int grp = lane >> 2;

    float acc[2][8][4];
#pragma unroll
    for (int mf = 0; mf < 2; mf++)
#pragma unroll
        for (int nf = 0; nf < 8; nf++)
#pragma unroll
            for (int q = 0; q < 4; q++) acc[mf][nf][q] = 0.0f;

    // per-thread load coords (4 chunks each for A and B)
    float4 ra[4], rb[4];
#pragma unroll
    for (int t = 0; t < 4; t++) {
        int idx = tid + t * 256;
        int m = idx >> 3, c4 = idx & 7;
        int gr = rowBase + m;
        ra[t] = (gr < Nrows) ? *(const float4*)(A + (size_t)gr * K + c4 * 4)
                             : make_float4(0.f, 0.f, 0.f, 0.f);
        int k = idx >> 5, b4 = idx & 31;
        rb[t] = *(const float4*)(W + (size_t)k * M + colBase + b4 * 4);
    }

    for (int k0 = 0; k0 < K; k0 += 32) {
        // store current regs -> smem (with tf32 convert)
#pragma unroll
        for (int t = 0; t < 4; t++) {
            int idx = tid + t * 256;
            int m = idx >> 3, c4 = idx & 7;
            As[m][c4 * 4 + 0] = f2tf32(ra[t].x);
            As[m][c4 * 4 + 1] = f2tf32(ra[t].y);
            As[m][c4 * 4 + 2] = f2tf32(ra[t].z);
            As[m][c4 * 4 + 3] = f2tf32(ra[t].w);
            int k = idx >> 5, b4 = idx & 31;
            Bs[k][b4 * 4 + 0] = f2tf32(rb[t].x);
            Bs[k][b4 * 4 + 1] = f2tf32(rb[t].y);
            Bs[k][b4 * 4 + 2] = f2tf32(rb[t].z);
            Bs[k][b4 * 4 + 3] = f2tf32(rb[t].w);
        }
        __syncthreads();
        // prefetch next slab (overlaps with MMA below)
        if (k0 + 32 < K) {
#pragma unroll
            for (int t = 0; t < 4; t++) {
                int idx = tid + t * 256;
                int m = idx >> 3, c4 = idx & 7;
                int gr = rowBase + m;
                ra[t] = (gr < Nrows)
                        ? *(const float4*)(A + (size_t)gr * K + (k0 + 32) + c4 * 4)
                        : make_float4(0.f, 0.f, 0.f, 0.f);
                int k = idx >> 5, b4 = idx & 31;
                rb[t] = *(const float4*)(W + (size_t)(k0 + 32 + k) * M + colBase + b4 * 4);
            }
        }
#pragma unroll
        for (int k8 = 0; k8 < 4; k8++) {
            uint32_t a[2][4];
#pragma unroll
            for (int mf = 0; mf < 2; mf++) {
                int mrow = warpRow * 32 + mf * 16 + grp;
                a[mf][0] = As[mrow][k8 * 8 + tig];
                a[mf][1] = As[mrow + 8][k8 * 8 + tig];
                a[mf][2] = As[mrow][k8 * 8 + tig + 4];
                a[mf][3] = As[mrow + 8][k8 * 8 + tig + 4];
            }
#pragma unroll
            for (int nf = 0; nf < 8; nf++) {
                int ncol = warpCol * 64 + nf * 8 + grp;
                uint32_t b0 = Bs[k8 * 8 + tig][ncol];
                uint32_t b1 = Bs[k8 * 8 + tig + 4][ncol];
                mma_tf32(acc[0][nf], a[0], b0, b1);
                mma_tf32(acc[1][nf], a[1], b0, b1);
            }
        }
        __syncthreads();
    }

#pragma unroll
    for (int mf = 0; mf < 2; mf++) {
        int row0 = rowBase + warpRow * 32 + mf * 16 + grp;
#pragma unroll
        for (int nf = 0; nf < 8; nf++) {
            int col = colBase + warpCol * 64 + nf * 8 + tig * 2;
            float2 v0 = make_float2(acc[mf][nf][0], acc[mf][nf][1]);
            float2 v1 = make_float2(acc[mf][nf][2], acc[mf][nf][3]);
            if constexpr (EPI == 1) {
                float2 s2 = *(const float2*)(g_s1 + col);
                float2 o2 = *(const float2*)(g_o1 + col);
                v0.x = fmaxf(fmaf(v0.x, s2.x, o2.x), 0.0f);
                v0.y = fmaxf(fmaf(v0.y, s2.y, o2.y), 0.0f);
                v1.x = fmaxf(fmaf(v1.x, s2.x, o2.x), 0.0f);
                v1.y = fmaxf(fmaf(v1.y, s2.y, o2.y), 0.0f);
            }
            if (row0 < Nrows)     *(float2*)(OUT + (size_t)row0 * M + col) = v0;
            if (row0 + 8 < Nrows) *(float2*)(OUT + (size_t)(row0 + 8) * M + col) = v1;
        }
    }
}

// ---------------- TF32 GEMM, N=40 (layer 3): 128x40 tile, 8 row-warps ------------
// A row-major [Nrows,256], W row-major [256,40]. OUT row stride 40. No epilogue.
template <int ASEL>
__global__ void __launch_bounds__(256, 2)
k_gemm_tf32_n40(const float* __restrict__ Aext, const float* __restrict__ W,
                int Nrows) {
    const float* A = selbuf_c<ASEL>(Aext);
    constexpr int K = 256, M = 40;
    __shared__ uint32_t As[128][36];
    __shared__ uint32_t Bs[32][44];

    const int tid  = threadIdx.x;
    const int warp = tid >> 5;      // 8 warps x 16 rows
    const int lane = tid & 31;
    const int rowBase = blockIdx.x * 128;
    const int tig = lane & 3;
    const int grp = lane >> 2;

    float acc[5][4];
#pragma unroll
    for (int nf = 0; nf < 5; nf++)
#pragma unroll
        for (int q = 0; q < 4; q++) acc[nf][q] = 0.0f;

    for (int k0 = 0; k0 < K; k0 += 32) {
        // A: 128 rows x 8 float4 = 1024 chunks
#pragma unroll
        for (int idx = tid; idx < 1024; idx += 256) {
            int m = idx >> 3, c4 = idx & 7;
            int gr = rowBase + m;
            float4 v = make_float4(0.f, 0.f, 0.f, 0.f);
            if (gr < Nrows) v = *(const float4*)(A + (size_t)gr * K + k0 + c4 * 4);
            As[m][c4 * 4 + 0] = f2tf32(v.x);
            As[m][c4 * 4 + 1] = f2tf32(v.y);
            As[m][c4 * 4 + 2] = f2tf32(v.z);
            As[m][c4 * 4 + 3] = f2tf32(v.w);
        }
        // B: 32 k-rows x 10 float4 = 320 chunks
        for (int idx = tid; idx < 320; idx += 256) {
            int k = idx / 10, b4 = idx % 10;
            float4 v = *(const float4*)(W + (size_t)(k0 + k) * M + b4 * 4);
            Bs[k][b4 * 4 + 0] = f2tf32(v.x);
            Bs[k][b4 * 4 + 1] = f2tf32(v.y);
            Bs[k][b4 * 4 + 2] = f2tf32(v.z);
            Bs[k][b4 * 4 + 3] = f2tf32(v.w);
        }
        __syncthreads();
#pragma unroll
        for (int k8 = 0; k8 < 4; k8++) {
            int mrow = warp * 16 + grp;
            uint32_t a[4];
            a[0] = As[mrow][k8 * 8 + tig];
            a[1] = As[mrow + 8][k8 * 8 + tig];
            a[2] = As[mrow][k8 * 8 + tig + 4];
            a[3] = As[mrow + 8][k8 * 8 + tig + 4];
#pragma unroll
            for (int nf = 0; nf < 5; nf++) {
                int ncol = nf * 8 + grp;
                uint32_t b0 = Bs[k8 * 8 + tig][ncol];
                uint32_t b1 = Bs[k8 * 8 + tig + 4][ncol];
                mma_tf32(acc[nf], a, b0, b1);
            }
        }
        __syncthreads();
    }

    int row0 = rowBase + warp * 16 + grp;
#pragma unroll
    for (int nf = 0; nf < 5; nf++) {
        int col = nf * 8 + tig * 2;
        if (row0 < Nrows)
            *(float2*)(g_b0 + (size_t)row0 * M + col) =
                make_float2(acc[nf][0], acc[nf][1]);
        if (row0 + 8 < Nrows)
            *(float2*)(g_b0 + (size_t)(row0 + 8) * M + col) =
                make_float2(acc[nf][2], acc[nf][3]);
    }
}

// ---------------- final: logits = g_b1 + b3; log_softmax over 40 cols ------------
__global__ void k_logsoftmax(const float* __restrict__ b3, float* __restrict__ OUT) {
    int warp = threadIdx.x / 32;
    int lane = threadIdx.x % 32;
    int row = blockIdx.x * 8 + warp;
    if (row >= NN) return;
    const float* p = g_b1 + (size_t)row * D_OUT;
    float x0 = p[lane] + b3[lane];
    float x1 = -1e30f;
    if (lane < 8) x1 = p[32 + lane] + b3[32 + lane];
    float mx = fmaxf(x0, x1);
#pragma unroll
    for (int o = 16; o > 0; o >>= 1)
        mx = fmaxf(mx, __shfl_xor_sync(0xffffffff, mx, o));
    float s = __expf(x0 - mx) + ((lane < 8) ? __expf(x1 - mx) : 0.0f);
#pragma unroll
    for (int o = 16; o > 0; o >>= 1)
        s += __shfl_xor_sync(0xffffffff, s, o);
    float ls = __logf(s);
    float* q = OUT + (size_t)row * D_OUT;
    q[lane] = x0 - mx - ls;
    if (lane < 8) q[32 + lane] = x1 - mx - ls;
}

// ---------------- launch (kernel launches ONLY) ----------------------------------
extern "C" void kernel_launch(void* const* d_in, const int* in_sizes, int n_in,
                              void* d_out, int out_size) {
    const float* x  = (const float*)d_in[0];
    const int*   ei = (const int*)d_in[1];   // int32 (JAX x64 disabled)
    const float* W1 = (const float*)d_in[2];
    const float* b1 = (const float*)d_in[3];
    const float* g1 = (const float*)d_in[4];
    const float* be1 = (const float*)d_in[5];
    const float* m1 = (const float*)d_in[6];
    const float* v1 = (const float*)d_in[7];
    const float* W2 = (const float*)d_in[8];
    const float* b2 = (const float*)d_in[9];
    const float* g2 = (const float*)d_in[10];
    const float* be2 = (const float*)d_in[11];
    const float* m2 = (const float*)d_in[12];
    const float* v2 = (const float*)d_in[13];
    const float* W3 = (const float*)d_in[14];
    const float* b3 = (const float*)d_in[15];
    float* out = (float*)d_out;

    int E = in_sizes[1] / 2;

    bool emb_in_out = ((long long)out_size >= (long long)NN * (D_OUT + D_H));
    float* emb = out + (size_t)NN * D_OUT;

    const int T = 256;
    int nblk = (NN + T - 1) / T;
    int eblk = (E + T - 1) / T;
    int ls_grid = (NN + 7) / 8;
    dim3 gemm_h((NN + 127) / 128, D_H / 128);
    int gemm_o_grid = (NN + 127) / 128;
    int agg32_grid = (NN + 7) / 8;     // TPR=32, 8 rows/block
    int agg40_grid = (NN + 15) / 16;   // TPR=16, 16 rows/block

    // ---- CSR build + BN params ----
    k_zero_counts<<<nblk, T>>>();
    k_count<<<eblk, T>>>(ei, E);
    k_scan1<<<NB_SCAN, 256>>>();
    k_scan2<<<1, 1024>>>();
    k_scan3<<<NB_SCAN, 256>>>(E);
    k_norms<<<nblk, T>>>();
    k_fill<<<eblk, T>>>(ei, E);
    k_bnparams<<<1, 256>>>(b1, g1, be1, m1, v1, b2, g2, be2, m2, v2);

    // ---- layer 1: g_b2 = agg(x) [128 cols]; g_b1 = relu(bn1(g_b2@W1)) [tf32] ----
    k_csr_agg<32, 32, 32, 3, 2, 0><<<agg32_grid, T>>>(x, nullptr, 0);
    k_gemm_tf32<2, 1, 1><<<gemm_h, T>>>(nullptr, W1, nullptr, NN, D_IN, D_H);

    // ---- layer 2: g_b0 = g_b1@W2 [tf32]; emb = relu(bn2(agg(g_b0))), 2 passes ---
    k_gemm_tf32<1, 0, 0><<<gemm_h, T>>>(nullptr, W2, nullptr, NN, D_H, D_H);
    if (emb_in_out) {
        k_csr_agg<32, 32, 64, 0, 3, 1><<<agg32_grid, T>>>(nullptr, emb, 0);
        k_csr_agg<32, 32, 64, 0, 3, 1><<<agg32_grid, T>>>(nullptr, emb, 32);
    } else {
        k_csr_agg<32, 32, 64, 0, 2, 1><<<agg32_grid, T>>>(nullptr, nullptr, 0);
        k_csr_agg<32, 32, 64, 0, 2, 1><<<agg32_grid, T>>>(nullptr, nullptr, 32);
    }

    // ---- layer 3: g_b0 = emb@W3 (40 cols, tf32); g_b1 = agg; log_softmax ----
    if (emb_in_out)
        k_gemm_tf32_n40<3><<<gemm_o_grid, T>>>(emb, W3, NN);
    else
        k_gemm_tf32_n40<2><<<gemm_o_grid, T>>>(nullptr, W3, NN);
    k_csr_agg<10, 16, 10, 0, 1, 0><<<agg40_grid, T>>>(nullptr, nullptr, 0);
    k_logsoftmax<<<ls_grid, T>>>(b3, out);
}

// round 12
// speedup vs baseline: 9.7058x; 1.0532x over previous
#include <cuda_runtime.h>
#include <cuda_bf16.h>
#include <math.h>
#include <stdint.h>

#define NN 169343
#define EE_MAX 2400000
#define D_IN 128
#define D_H  256
#define D_OUT 40
#define EPS 1e-5f
#define NB_SCAN ((NN + 255) / 256)   // 662

// ---------------- scratch (allocation-free __device__ globals) -------------------
__device__ float g_dinv[NN];
__device__ float g_selfnorm[NN];
__device__ int   g_counts[NN];
__device__ int   g_cursor[NN];
__device__ int   g_rowptr[NN + 1];
__device__ int   g_partial[NB_SCAN];
__device__ int2  g_csr[EE_MAX];            // {src, w-as-bits} interleaved
__device__ float g_s1[D_H], g_o1[D_H];     // fused BN1 params
__device__ float g_s2[D_H], g_o2[D_H];     // fused BN2 params
__device__ float g_b0[(size_t)NN * D_H];   // H (gemm output)
__device__ float g_b1[(size_t)NN * D_H];   // act1 / logits-agg
__device__ float g_b2[(size_t)NN * D_H];   // agg(x) / emb fallback

template <int SEL>
__device__ __forceinline__ float* selbuf(float* ext) {
    if constexpr (SEL == 0) return g_b0;
    else if constexpr (SEL == 1) return g_b1;
    else if constexpr (SEL == 2) return g_b2;
    else return ext;
}
template <int SEL>
__device__ __forceinline__ const float* selbuf_c(const float* ext) {
    if constexpr (SEL == 0) return g_b0;
    else if constexpr (SEL == 1) return g_b1;
    else if constexpr (SEL == 2) return g_b2;
    else return ext;
}

// ---------------- CSR build ------------------------------------------------------
__global__ void k_zero_counts() {
    int i = blockIdx.x * blockDim.x + threadIdx.x;
    if (i < NN) g_counts[i] = 0;
}
__global__ void k_count(const int* __restrict__ ei, int E) {
    int e = blockIdx.x * blockDim.x + threadIdx.x;
    if (e < E) atomicAdd(&g_counts[ei[E + e]], 1);
}
__global__ void k_scan1() {
    __shared__ int s[256];
    int gid = blockIdx.x * 256 + threadIdx.x;
    int v = (gid < NN) ? g_counts[gid] : 0;
    s[threadIdx.x] = v;
    __syncthreads();
#pragma unroll
    for (int off = 1; off < 256; off <<= 1) {
        int t = (threadIdx.x >= off) ? s[threadIdx.x - off] : 0;
        __syncthreads();
        s[threadIdx.x] += t;
        __syncthreads();
    }
    if (gid < NN) g_rowptr[gid] = s[threadIdx.x] - v;   // exclusive
    if (threadIdx.x == 255) g_partial[blockIdx.x] = s[255];
}
__global__ void k_scan2() {
    __shared__ int s[1024];
    int v = (threadIdx.x < NB_SCAN) ? g_partial[threadIdx.x] : 0;
    s[threadIdx.x] = v;
    __syncthreads();
#pragma unroll
    for (int off = 1; off < 1024; off <<= 1) {
        int t = (threadIdx.x >= off) ? s[threadIdx.x - off] : 0;
        __syncthreads();
        s[threadIdx.x] += t;
        __syncthreads();
    }
    if (threadIdx.x < NB_SCAN) g_partial[threadIdx.x] = s[threadIdx.x] - v;
}
__global__ void k_scan3(int E) {
    int gid = blockIdx.x * 256 + threadIdx.x;
    if (gid < NN) g_rowptr[gid] += g_partial[blockIdx.x];
    if (gid == 0) g_rowptr[NN] = E;
}
__global__ void k_norms() {
    int i = blockIdx.x * blockDim.x + threadIdx.x;
    if (i < NN) {
        int r0 = g_rowptr[i];
        float d = (float)(g_rowptr[i + 1] - r0 + 1);
        g_dinv[i]     = rsqrtf(d);
        g_selfnorm[i] = 1.0f / d;
        g_cursor[i]   = r0;
    }
}
__global__ void k_fill(const int* __restrict__ ei, int E) {
    int e = blockIdx.x * blockDim.x + threadIdx.x;
    if (e < E) {
        int src = ei[e];
        int dst = ei[E + e];
        int pos = atomicAdd(&g_cursor[dst], 1);
        float w = g_dinv[src] * g_dinv[dst];
        g_csr[pos] = make_int2(src, __float_as_int(w));
    }
}
__global__ void k_bnparams(const float* __restrict__ b1, const float* __restrict__ g1,
                           const float* __restrict__ be1, const float* __restrict__ m1,
                           const float* __restrict__ v1,
                           const float* __restrict__ b2, const float* __restrict__ g2,
                           const float* __restrict__ be2, const float* __restrict__ m2,
                           const float* __restrict__ v2) {
    int c = threadIdx.x;
    if (c < D_H) {
        float s = g1[c] * rsqrtf(v1[c] + EPS);
        g_s1[c] = s;
        g_o1[c] = be1[c] + (b1[c] - m1[c]) * s;
        s = g2[c] * rsqrtf(v2[c] + EPS);
        g_s2[c] = s;
        g_o2[c] = be2[c] + (b2[c] - m2[c]) * s;
    }
}

// ---------------- CSR aggregation ------------------------------------------------
template <int C4, int TPR, int ROWST4, int SRCSEL, int DSTSEL, int EPI>
__global__ void k_csr_agg(const float* __restrict__ srcExt, float* dstExt, int colOff4) {
    const float* __restrict__ SRC = selbuf_c<SRCSEL>(srcExt);
    float* DST = selbuf<DSTSEL>(dstExt);
    constexpr int RPB = 256 / TPR;
    int row = blockIdx.x * RPB + threadIdx.x / TPR;
    int c   = threadIdx.x % TPR;
    if (row >= NN || c >= C4) return;
    int col4 = colOff4 + c;

    float sn = g_selfnorm[row];
    float4 h = *((const float4*)(SRC + (size_t)row * (ROWST4 * 4)) + col4);
    float4 acc = make_float4(h.x * sn, h.y * sn, h.z * sn, h.w * sn);

    int e0 = g_rowptr[row], e1 = g_rowptr[row + 1];
#pragma unroll 2
    for (int e = e0; e < e1; e++) {
        int2 p = g_csr[e];
        float w = __int_as_float(p.y);
        float4 v = *((const float4*)(SRC + (size_t)p.x * (ROWST4 * 4)) + col4);
        acc.x = fmaf(v.x, w, acc.x);
        acc.y = fmaf(v.y, w, acc.y);
        acc.z = fmaf(v.z, w, acc.z);
        acc.w = fmaf(v.w, w, acc.w);
    }
    if constexpr (EPI == 1) {
        float4 s4 = *((const float4*)g_s2 + col4);
        float4 o4 = *((const float4*)g_o2 + col4);
        acc.x = fmaxf(fmaf(acc.x, s4.x, o4.x), 0.0f);
        acc.y = fmaxf(fmaf(acc.y, s4.y, o4.y), 0.0f);
        acc.z = fmaxf(fmaf(acc.z, s4.z, o4.z), 0.0f);
        acc.w = fmaxf(fmaf(acc.w, s4.w, o4.w), 0.0f);
    }
    *((float4*)(DST + (size_t)row * (ROWST4 * 4)) + col4) = acc;
}

// ---------------- tf32 helpers ---------------------------------------------------
__device__ __forceinline__ uint32_t f2tf32(float f) {
    uint32_t r;
    asm("cvt.rna.tf32.f32 %0, %1;" : "=r"(r) : "f"(f));
    return r;
}
__device__ __forceinline__ void mma_tf32(float* c, const uint32_t* a,
                                         uint32_t b0, uint32_t b1) {
    asm volatile(
        "mma.sync.aligned.m16n8k8.row.col.f32.tf32.tf32.f32 "
        "{%0,%1,%2,%3}, {%4,%5,%6,%7}, {%8,%9}, {%0,%1,%2,%3};"
        : "+f"(c[0]), "+f"(c[1]), "+f"(c[2]), "+f"(c[3])
        : "r"(a[0]), "r"(a[1]), "r"(a[2]), "r"(a[3]), "r"(b0), "r"(b1));
}

// ---------------- TF32 GEMM: 128x128 tile, double-buffered dynamic smem ----------
// 8 warps (4x2), warp 32x64. A row-major [Nrows,K], W row-major [K,M] (M=256).
// Stage = As[128][36] + Bs[32][136] u32. One __syncthreads per K-slab.
#define AS_U32 (128 * 36)
#define BS_U32 (32 * 136)
#define STAGE_U32 (AS_U32 + BS_U32)
#define GEMM_SMEM_BYTES (2 * STAGE_U32 * 4)

template <int ASEL, int OUTSEL, int EPI>
__global__ void __launch_bounds__(256, 2)
k_gemm_tf32(const float* __restrict__ Aext, const float* __restrict__ W,
            float* outExt, int Nrows, int K, int M) {
    const float* A = selbuf_c<ASEL>(Aext);
    float* OUT = selbuf<OUTSEL>(outExt);
    extern __shared__ uint32_t dynsmem[];

    const int tid  = threadIdx.x;
    const int warp = tid >> 5;
    const int lane = tid & 31;
    const int warpRow = warp & 3;
    const int warpCol = warp >> 2;
    const int rowBase = blockIdx.x * 128;
    const int colBase = blockIdx.y * 128;
    const int tig = lane & 3;
    const int grp = lane >> 2;

    float acc[2][8][4];
#pragma unroll
    for (int mf = 0; mf < 2; mf++)
#pragma unroll
        for (int nf = 0; nf < 8; nf++)
#pragma unroll
            for (int q = 0; q < 4; q++) acc[mf][nf][q] = 0.0f;

    float4 ra[4], rb[4];
    // load slab 0
#pragma unroll
    for (int t = 0; t < 4; t++) {
        int idx = tid + t * 256;
        int m = idx >> 3, c4 = idx & 7;
        int gr = rowBase + m;
        ra[t] = (gr < Nrows) ? *(const float4*)(A + (size_t)gr * K + c4 * 4)
                             : make_float4(0.f, 0.f, 0.f, 0.f);
        int k = idx >> 5, b4 = idx & 31;
        rb[t] = *(const float4*)(W + (size_t)k * M + colBase + b4 * 4);
    }
    // store slab 0 -> stage 0
    {
        uint32_t* As = dynsmem;
        uint32_t* Bs = dynsmem + AS_U32;
#pragma unroll
        for (int t = 0; t < 4; t++) {
            int idx = tid + t * 256;
            int m = idx >> 3, c4 = idx & 7;
            As[m * 36 + c4 * 4 + 0] = f2tf32(ra[t].x);
            As[m * 36 + c4 * 4 + 1] = f2tf32(ra[t].y);
            As[m * 36 + c4 * 4 + 2] = f2tf32(ra[t].z);
            As[m * 36 + c4 * 4 + 3] = f2tf32(ra[t].w);
            int k = idx >> 5, b4 = idx & 31;
            Bs[k * 136 + b4 * 4 + 0] = f2tf32(rb[t].x);
            Bs[k * 136 + b4 * 4 + 1] = f2tf32(rb[t].y);
            Bs[k * 136 + b4 * 4 + 2] = f2tf32(rb[t].z);
            Bs[k * 136 + b4 * 4 + 3] = f2tf32(rb[t].w);
        }
    }
    __syncthreads();

    const int niter = K >> 5;
    for (int i = 0; i < niter; i++) {
        // prefetch slab i+1 to regs (overlaps MMA below)
        if (i + 1 < niter) {
            int kb = (i + 1) << 5;
#pragma unroll
            for (int t = 0; t < 4; t++) {
                int idx = tid + t * 256;
                int m = idx >> 3, c4 = idx & 7;
                int gr = rowBase + m;
                ra[t] = (gr < Nrows)
                        ? *(const float4*)(A + (size_t)gr * K + kb + c4 * 4)
                        : make_float4(0.f, 0.f, 0.f, 0.f);
                int k = idx >> 5, b4 = idx & 31;
                rb[t] = *(const float4*)(W + (size_t)(kb + k) * M + colBase + b4 * 4);
            }
        }
        // MMA on stage i&1
        {
            const uint32_t* As = dynsmem + (i & 1) * STAGE_U32;
            const uint32_t* Bs = As + AS_U32;
#pragma unroll
            for (int k8 = 0; k8 < 4; k8++) {
                uint32_t a[2][4];
#pragma unroll
                for (int mf = 0; mf < 2; mf++) {
                    int mrow = warpRow * 32 + mf * 16 + grp;
                    a[mf][0] = As[mrow * 36 + k8 * 8 + tig];
                    a[mf][1] = As[(mrow + 8) * 36 + k8 * 8 + tig];
                    a[mf][2] = As[mrow * 36 + k8 * 8 + tig + 4];
                    a[mf][3] = As[(mrow + 8) * 36 + k8 * 8 + tig + 4];
                }
#pragma unroll
                for (int nf = 0; nf < 8; nf++) {
                    int ncol = warpCol * 64 + nf * 8 + grp;
                    uint32_t b0 = Bs[(k8 * 8 + tig) * 136 + ncol];
                    uint32_t b1 = Bs[(k8 * 8 + tig + 4) * 136 + ncol];
                    mma_tf32(acc[0][nf], a[0], b0, b1);
                    mma_tf32(acc[1][nf], a[1], b0, b1);
                }
            }
        }
        // store slab i+1 -> stage (i+1)&1
        if (i + 1 < niter) {
            uint32_t* As = dynsmem + ((i + 1) & 1) * STAGE_U32;
            uint32_t* Bs = As + AS_U32;
#pragma unroll
            for (int t = 0; t < 4; t++) {
                int idx = tid + t * 256;
                int m = idx >> 3, c4 = idx & 7;
                As[m * 36 + c4 * 4 + 0] = f2tf32(ra[t].x);
                As[m * 36 + c4 * 4 + 1] = f2tf32(ra[t].y);
                As[m * 36 + c4 * 4 + 2] = f2tf32(ra[t].z);
                As[m * 36 + c4 * 4 + 3] = f2tf32(ra[t].w);
                int k = idx >> 5, b4 = idx & 31;
                Bs[k * 136 + b4 * 4 + 0] = f2tf32(rb[t].x);
                Bs[k * 136 + b4 * 4 + 1] = f2tf32(rb[t].y);
                Bs[k * 136 + b4 * 4 + 2] = f2tf32(rb[t].z);
                Bs[k * 136 + b4 * 4 + 3] = f2tf32(rb[t].w);
            }
            __syncthreads();
        }
    }

#pragma unroll
    for (int mf = 0; mf < 2; mf++) {
        int row0 = rowBase + warpRow * 32 + mf * 16 + grp;
#pragma unroll
        for (int nf = 0; nf < 8; nf++) {
            int col = colBase + warpCol * 64 + nf * 8 + tig * 2;
            float2 v0 = make_float2(acc[mf][nf][0], acc[mf][nf][1]);
            float2 v1 = make_float2(acc[mf][nf][2], acc[mf][nf][3]);
            if constexpr (EPI == 1) {
                float2 s2 = *(const float2*)(g_s1 + col);
                float2 o2 = *(const float2*)(g_o1 + col);
                v0.x = fmaxf(fmaf(v0.x, s2.x, o2.x), 0.0f);
                v0.y = fmaxf(fmaf(v0.y, s2.y, o2.y), 0.0f);
                v1.x = fmaxf(fmaf(v1.x, s2.x, o2.x), 0.0f);
                v1.y = fmaxf(fmaf(v1.y, s2.y, o2.y), 0.0f);
            }
            if (row0 < Nrows)     *(float2*)(OUT + (size_t)row0 * M + col) = v0;
            if (row0 + 8 < Nrows) *(float2*)(OUT + (size_t)(row0 + 8) * M + col) = v1;
        }
    }
}

// ---------------- TF32 GEMM, N=40 (layer 3): 128x40 tile, reg-prefetch -----------
template <int ASEL>
__global__ void __launch_bounds__(256, 2)
k_gemm_tf32_n40(const float* __restrict__ Aext, const float* __restrict__ W,
                int Nrows) {
    const float* A = selbuf_c<ASEL>(Aext);
    constexpr int K = 256, M = 40;
    __shared__ uint32_t As[128][36];
    __shared__ uint32_t Bs[32][44];

    const int tid  = threadIdx.x;
    const int warp = tid >> 5;
    const int lane = tid & 31;
    const int rowBase = blockIdx.x * 128;
    const int tig = lane & 3;
    const int grp = lane >> 2;

    float acc[5][4];
#pragma unroll
    for (int nf = 0; nf < 5; nf++)
#pragma unroll
        for (int q = 0; q < 4; q++) acc[nf][q] = 0.0f;

    float4 ra[4];
    float4 rb[2];
#pragma unroll
    for (int t = 0; t < 4; t++) {
        int idx = tid + t * 256;
        int m = idx >> 3, c4 = idx & 7;
        int gr = rowBase + m;
        ra[t] = (gr < Nrows) ? *(const float4*)(A + (size_t)gr * K + c4 * 4)
                             : make_float4(0.f, 0.f, 0.f, 0.f);
    }
#pragma unroll
    for (int t = 0; t < 2; t++) {
        int idx = tid + t * 256;
        if (idx < 320) {
            int k = idx / 10, b4 = idx % 10;
            rb[t] = *(const float4*)(W + (size_t)k * M + b4 * 4);
        }
    }

    for (int k0 = 0; k0 < K; k0 += 32) {
        // store current regs
#pragma unroll
        for (int t = 0; t < 4; t++) {
            int idx = tid + t * 256;
            int m = idx >> 3, c4 = idx & 7;
            As[m][c4 * 4 + 0] = f2tf32(ra[t].x);
            As[m][c4 * 4 + 1] = f2tf32(ra[t].y);
            As[m][c4 * 4 + 2] = f2tf32(ra[t].z);
            As[m][c4 * 4 + 3] = f2tf32(ra[t].w);
        }
#pragma unroll
        for (int t = 0; t < 2; t++) {
            int idx = tid + t * 256;
            if (idx < 320) {
                int k = idx / 10, b4 = idx % 10;
                Bs[k][b4 * 4 + 0] = f2tf32(rb[t].x);
                Bs[k][b4 * 4 + 1] = f2tf32(rb[t].y);
                Bs[k][b4 * 4 + 2] = f2tf32(rb[t].z);
                Bs[k][b4 * 4 + 3] = f2tf32(rb[t].w);
            }
        }
        __syncthreads();
        // prefetch next slab
        if (k0 + 32 < K) {
#pragma unroll
            for (int t = 0; t < 4; t++) {
                int idx = tid + t * 256;
                int m = idx >> 3, c4 = idx & 7;
                int gr = rowBase + m;
                ra[t] = (gr < Nrows)
                        ? *(const float4*)(A + (size_t)gr * K + (k0 + 32) + c4 * 4)
                        : make_float4(0.f, 0.f, 0.f, 0.f);
            }
#pragma unroll
            for (int t = 0; t < 2; t++) {
                int idx = tid + t * 256;
                if (idx < 320) {
                    int k = idx / 10, b4 = idx % 10;
                    rb[t] = *(const float4*)(W + (size_t)(k0 + 32 + k) * M + b4 * 4);
                }
            }
        }
#pragma unroll
        for (int k8 = 0; k8 < 4; k8++) {
            int mrow = warp * 16 + grp;
            uint32_t a[4];
            a[0] = As[mrow][k8 * 8 + tig];
            a[1] = As[mrow + 8][k8 * 8 + tig];
            a[2] = As[mrow][k8 * 8 + tig + 4];
            a[3] = As[mrow + 8][k8 * 8 + tig + 4];
#pragma unroll
            for (int nf = 0; nf < 5; nf++) {
                int ncol = nf * 8 + grp;
                uint32_t b0 = Bs[k8 * 8 + tig][ncol];
                uint32_t b1 = Bs[k8 * 8 + tig + 4][ncol];
                mma_tf32(acc[nf], a, b0, b1);
            }
        }
        __syncthreads();
    }

    int row0 = rowBase + warp * 16 + grp;
#pragma unroll
    for (int nf = 0; nf < 5; nf++) {
        int col = nf * 8 + tig * 2;
        if (row0 < Nrows)
            *(float2*)(g_b0 + (size_t)row0 * M + col) =
                make_float2(acc[nf][0], acc[nf][1]);
        if (row0 + 8 < Nrows)
            *(float2*)(g_b0 + (size_t)(row0 + 8) * M + col) =
                make_float2(acc[nf][2], acc[nf][3]);
    }
}

// ---------------- final: logits = g_b1 + b3; log_softmax over 40 cols ------------
__global__ void k_logsoftmax(const float* __restrict__ b3, float* __restrict__ OUT) {
    int warp = threadIdx.x / 32;
    int lane = threadIdx.x % 32;
    int row = blockIdx.x * 8 + warp;
    if (row >= NN) return;
    const float* p = g_b1 + (size_t)row * D_OUT;
    float x0 = p[lane] + b3[lane];
    float x1 = -1e30f;
    if (lane < 8) x1 = p[32 + lane] + b3[32 + lane];
    float mx = fmaxf(x0, x1);
#pragma unroll
    for (int o = 16; o > 0; o >>= 1)
        mx = fmaxf(mx, __shfl_xor_sync(0xffffffff, mx, o));
    float s = __expf(x0 - mx) + ((lane < 8) ? __expf(x1 - mx) : 0.0f);
#pragma unroll
    for (int o = 16; o > 0; o >>= 1)
        s += __shfl_xor_sync(0xffffffff, s, o);
    float ls = __logf(s);
    float* q = OUT + (size_t)row * D_OUT;
    q[lane] = x0 - mx - ls;
    if (lane < 8) q[32 + lane] = x1 - mx - ls;
}

// ---------------- launch (kernel launches ONLY + func attrs) ---------------------
extern "C" void kernel_launch(void* const* d_in, const int* in_sizes, int n_in,
                              void* d_out, int out_size) {
    const float* x  = (const float*)d_in[0];
    const int*   ei = (const int*)d_in[1];   // int32 (JAX x64 disabled)
    const float* W1 = (const float*)d_in[2];
    const float* b1 = (const float*)d_in[3];
    const float* g1 = (const float*)d_in[4];
    const float* be1 = (const float*)d_in[5];
    const float* m1 = (const float*)d_in[6];
    const float* v1 = (const float*)d_in[7];
    const float* W2 = (const float*)d_in[8];
    const float* b2 = (const float*)d_in[9];
    const float* g2 = (const float*)d_in[10];
    const float* be2 = (const float*)d_in[11];
    const float* m2 = (const float*)d_in[12];
    const float* v2 = (const float*)d_in[13];
    const float* W3 = (const float*)d_in[14];
    const float* b3 = (const float*)d_in[15];
    float* out = (float*)d_out;

    int E = in_sizes[1] / 2;

    bool emb_in_out = ((long long)out_size >= (long long)NN * (D_OUT + D_H));
    float* emb = out + (size_t)NN * D_OUT;

    cudaFuncSetAttribute(k_gemm_tf32<2, 1, 1>,
                         cudaFuncAttributeMaxDynamicSharedMemorySize, GEMM_SMEM_BYTES);
    cudaFuncSetAttribute(k_gemm_tf32<1, 0, 0>,
                         cudaFuncAttributeMaxDynamicSharedMemorySize, GEMM_SMEM_BYTES);

    const int T = 256;
    int nblk = (NN + T - 1) / T;
    int eblk = (E + T - 1) / T;
    int ls_grid = (NN + 7) / 8;
    dim3 gemm_h((NN + 127) / 128, D_H / 128);
    int gemm_o_grid = (NN + 127) / 128;
    int agg32_grid = (NN + 7) / 8;     // TPR=32, 8 rows/block
    int agg40_grid = (NN + 15) / 16;   // TPR=16, 16 rows/block

    // ---- CSR build + BN params ----
    k_zero_counts<<<nblk, T>>>();
    k_count<<<eblk, T>>>(ei, E);
    k_scan1<<<NB_SCAN, 256>>>();
    k_scan2<<<1, 1024>>>();
    k_scan3<<<NB_SCAN, 256>>>(E);
    k_norms<<<nblk, T>>>();
    k_fill<<<eblk, T>>>(ei, E);
    k_bnparams<<<1, 256>>>(b1, g1, be1, m1, v1, b2, g2, be2, m2, v2);

    // ---- layer 1: g_b2 = agg(x) [128 cols]; g_b1 = relu(bn1(g_b2@W1)) [tf32] ----
    k_csr_agg<32, 32, 32, 3, 2, 0><<<agg32_grid, T>>>(x, nullptr, 0);
    k_gemm_tf32<2, 1, 1><<<gemm_h, T, GEMM_SMEM_BYTES>>>(nullptr, W1, nullptr,
                                                         NN, D_IN, D_H);

    // ---- layer 2: g_b0 = g_b1@W2 [tf32]; emb = relu(bn2(agg(g_b0))), 2 passes ---
    k_gemm_tf32<1, 0, 0><<<gemm_h, T, GEMM_SMEM_BYTES>>>(nullptr, W2, nullptr,
                                                         NN, D_H, D_H);
    if (emb_in_out) {
        k_csr_agg<32, 32, 64, 0, 3, 1><<<agg32_grid, T>>>(nullptr, emb, 0);
        k_csr_agg<32, 32, 64, 0, 3, 1><<<agg32_grid, T>>>(nullptr, emb, 32);
    } else {
        k_csr_agg<32, 32, 64, 0, 2, 1><<<agg32_grid, T>>>(nullptr, nullptr, 0);
        k_csr_agg<32, 32, 64, 0, 2, 1><<<agg32_grid, T>>>(nullptr, nullptr, 32);
    }

    // ---- layer 3: g_b0 = emb@W3 (40 cols, tf32); g_b1 = agg; log_softmax ----
    if (emb_in_out)
        k_gemm_tf32_n40<3><<<gemm_o_grid, T>>>(emb, W3, NN);
    else
        k_gemm_tf32_n40<2><<<gemm_o_grid, T>>>(nullptr, W3, NN);
    k_csr_agg<10, 16, 10, 0, 1, 0><<<agg40_grid, T>>>(nullptr, nullptr, 0);
    k_logsoftmax<<<ls_grid, T>>>(b3, out);
}